// round 4
// baseline (speedup 1.0000x reference)
#include <cuda_runtime.h>
#include <math.h>

#define N_SEQ 896
#define DH    3072
#define NC    64
#define NJ    127
#define DC    1024
#define INNER 512
#define NH    8
#define HD    64

typedef unsigned long long ull;

// ---------------- packed f32x2 helpers (FFMA2 — ptxas never emits; PTX only) ----
__device__ __forceinline__ ull pack2(float x, float y) {
    ull r;
    asm("mov.b64 %0, {%1, %2};" : "=l"(r) : "f"(x), "f"(y));
    return r;
}
__device__ __forceinline__ void fma2(ull& d, ull a, ull b) {
    asm("fma.rn.f32x2 %0, %1, %2, %0;" : "+l"(d) : "l"(a), "l"(b));
}
__device__ __forceinline__ float2 unpack2(ull v) {
    float2 f;
    asm("mov.b64 {%0, %1}, %2;" : "=f"(f.x), "=f"(f.y) : "l"(v));
    return f;
}

// ---------------- scratch (static device memory; no allocations) ----------------
__device__ float g_w[INNER];                       // Wo @ Wp
__device__ float g_ep[N_SEQ];                      // embeddings @ Wp
__device__ float g_bias;                           // bo @ Wp + bp
__device__ float g_wvpt[NH * DC];                  // [h][i] = Wkv_v(:,h*64+t) @ w_h
__device__ float g_vpnull[NH];
__device__ float g_lnq[(size_t)N_SEQ * DH];        // LN(embeddings)
__device__ float g_lnc[(size_t)NC * NJ * DC];      // LN(context)
__device__ float g_q[(size_t)N_SEQ * INNER];       // q projection
__device__ float g_k[(size_t)NC * NJ * INNER];     // k projection
__device__ float g_vpt[NC * NH * NJ];              // [c][h][j]

__device__ __forceinline__ float warpSum(float v) {
#pragma unroll
    for (int o = 16; o > 0; o >>= 1) v += __shfl_xor_sync(0xffffffffu, v, o);
    return v;
}

// ---------------- fused pre-pass: LN(embeddings) + all Wp dot products -----------
// blocks [0, 896): LN of embeddings row b
// blocks [896, 896+512): g_w[bid-896] = Wo row · Wp
// blocks [896+512, 896+512+896): g_ep
// last block: g_bias
__global__ void k_pre(const float* __restrict__ emb, const float* __restrict__ gamma,
                      const float* __restrict__ beta, const float* __restrict__ Wo,
                      const float* __restrict__ Wp, const float* __restrict__ bo,
                      const float* __restrict__ bp) {
    __shared__ float row[DH];
    __shared__ float red[18];
    int bid = blockIdx.x, t = threadIdx.x;
    if (bid >= N_SEQ) {
        // dot-product blocks
        int id = bid - N_SEQ;
        const float* a;
        if (id < 512)            a = Wo  + (size_t)id * DH;
        else if (id < 512+N_SEQ) a = emb + (size_t)(id - 512) * DH;
        else                     a = bo;
        float s = 0.f;
        for (int i = t; i < DH; i += 256) s = fmaf(a[i], Wp[i], s);
        s = warpSum(s);
        if ((t & 31) == 0) red[t >> 5] = s;
        __syncthreads();
        if (t == 0) {
            float S = 0.f;
#pragma unroll
            for (int i = 0; i < 8; i++) S += red[i];
            if (id < 512)              g_w[id] = S;
            else if (id < 512 + N_SEQ) g_ep[id - 512] = S;
            else                       g_bias = S + bp[0];
        }
        return;
    }
    // LN block
    const float* xr = emb + (size_t)bid * DH;
    float s = 0.f, ss = 0.f;
#pragma unroll
    for (int u = 0; u < 3; u++) {
        int idx = (t + u * 256) * 4;
        float4 v = *(const float4*)(xr + idx);
        row[idx] = v.x; row[idx+1] = v.y; row[idx+2] = v.z; row[idx+3] = v.w;
        s  += v.x + v.y + v.z + v.w;
        ss += v.x*v.x + v.y*v.y + v.z*v.z + v.w*v.w;
    }
    s = warpSum(s); ss = warpSum(ss);
    if ((t & 31) == 0) { red[t >> 5] = s; red[8 + (t >> 5)] = ss; }
    __syncthreads();
    if (t == 0) {
        float S = 0.f, SS = 0.f;
#pragma unroll
        for (int i = 0; i < 8; i++) { S += red[i]; SS += red[8 + i]; }
        float mu = S / DH;
        float var = SS / DH - mu * mu;
        red[16] = mu; red[17] = rsqrtf(var + 1e-5f);
    }
    __syncthreads();
    float mu = red[16], rstd = red[17];
    float* outr = g_lnq + (size_t)bid * DH;
#pragma unroll
    for (int u = 0; u < 3; u++) {
        int idx = (t + u * 256) * 4;
        float4 o;
        o.x = (row[idx]   - mu) * rstd * gamma[idx]   + beta[idx];
        o.y = (row[idx+1] - mu) * rstd * gamma[idx+1] + beta[idx+1];
        o.z = (row[idx+2] - mu) * rstd * gamma[idx+2] + beta[idx+2];
        o.w = (row[idx+3] - mu) * rstd * gamma[idx+3] + beta[idx+3];
        *(float4*)(outr + idx) = o;
    }
}

// ---------------- prep 2: Wv_p^T and vp_null (needs g_w) ----------------
__global__ void k_prep2(const float* __restrict__ Wkv, const float* __restrict__ null_v) {
    int bid = blockIdx.x, t = threadIdx.x;
    if (bid < 32) {
        int gid = bid * 256 + t;
        int h = gid >> 10, i = gid & 1023;
        const float* wrow = g_w + h * HD;
        const float* src  = Wkv + (size_t)i * (2 * INNER) + INNER + h * HD;
        float s = 0.f;
#pragma unroll
        for (int d = 0; d < HD; d++) s = fmaf(src[d], wrow[d], s);
        g_wvpt[h * DC + i] = s;
    } else if (t < NH) {
        float s = 0.f;
#pragma unroll
        for (int d = 0; d < HD; d++) s = fmaf(null_v[t * HD + d], g_w[t * HD + d], s);
        g_vpnull[t] = s;
    }
}

// ---------------- LN over context rows (1024) + fused vp ----------------
__global__ void k_ln_c(const float* __restrict__ x, const float* __restrict__ gamma,
                       const float* __restrict__ beta) {
    __shared__ float row[DC];
    __shared__ float red[18];
    int b = blockIdx.x, t = threadIdx.x;
    const float* xr = x + (size_t)b * DC;
    int idx = t * 4;
    float4 v = *(const float4*)(xr + idx);
    float s  = v.x + v.y + v.z + v.w;
    float ss = v.x*v.x + v.y*v.y + v.z*v.z + v.w*v.w;
    s = warpSum(s); ss = warpSum(ss);
    if ((t & 31) == 0) { red[t >> 5] = s; red[8 + (t >> 5)] = ss; }
    __syncthreads();
    if (t == 0) {
        float S = 0.f, SS = 0.f;
#pragma unroll
        for (int i = 0; i < 8; i++) { S += red[i]; SS += red[8 + i]; }
        float mu = S / DC;
        float var = SS / DC - mu * mu;
        red[16] = mu; red[17] = rsqrtf(var + 1e-5f);
    }
    __syncthreads();
    float mu = red[16], rstd = red[17];
    float4 o;
    o.x = (v.x - mu) * rstd * gamma[idx]   + beta[idx];
    o.y = (v.y - mu) * rstd * gamma[idx+1] + beta[idx+1];
    o.z = (v.z - mu) * rstd * gamma[idx+2] + beta[idx+2];
    o.w = (v.w - mu) * rstd * gamma[idx+3] + beta[idx+3];
    *(float4*)(&row[idx]) = o;
    *(float4*)(g_lnc + (size_t)b * DC + idx) = o;
    __syncthreads();
    int w = t >> 5, lane = t & 31;
    const float* wv = g_wvpt + w * DC;
    float acc = 0.f;
#pragma unroll
    for (int m = 0; m < 32; m++) acc = fmaf(row[lane + 32 * m], wv[lane + 32 * m], acc);
    acc = warpSum(acc);
    if (lane == 0) {
        int c = b / NJ, j = b % NJ;
        g_vpt[((size_t)c * NH + w) * NJ + j] = acc;
    }
}

// ---------------- fused SGEMM (FFMA2): q-proj + k-proj in one grid ----------------
// Tile 64(M) x 128(N), BK=16, 256 threads, 4x8 microtile (as 4x4 packed pairs).
__global__ void k_gemm_fused(const float* __restrict__ Wq, const float* __restrict__ Wkv) {
    __shared__ float As[16][68];
    __shared__ float Bs[16][128];
    int t = threadIdx.x, bid = blockIdx.x;
    const float *A, *B; float *C; int lda, ldb, K;
    int bm, bn;
    if (bid < 508) {
        bm = bid >> 2; bn = bid & 3;
        A = g_lnc; lda = DC; K = DC; B = Wkv; ldb = 2 * INNER; C = g_k;
    } else {
        int l = bid - 508; bm = l >> 2; bn = l & 3;
        A = g_lnq; lda = DH; K = DH; B = Wq; ldb = INNER; C = g_q;
    }
    int m0 = bm * 64, n0 = bn * 128;
    int tx = t & 15, ty = t >> 4;
    int ra = t >> 2, qa = t & 3;
    int kb = t >> 4, cb = t & 15;
    ull acc2[4][4];
#pragma unroll
    for (int i = 0; i < 4; i++)
#pragma unroll
        for (int j = 0; j < 4; j++) acc2[i][j] = 0ULL;

    const float* Aip = A + (size_t)(m0 + ra) * lda + qa * 4;
    const float* Bip = B + (size_t)kb * ldb + n0 + cb * 8;
    float4 ap  = *(const float4*)Aip;
    float4 bp0 = *(const float4*)Bip;
    float4 bp1 = *(const float4*)(Bip + 4);

    for (int k0 = 0; k0 < K; k0 += 16) {
        As[qa*4+0][ra] = ap.x; As[qa*4+1][ra] = ap.y;
        As[qa*4+2][ra] = ap.z; As[qa*4+3][ra] = ap.w;
        *(float4*)(&Bs[kb][cb*8])     = bp0;
        *(float4*)(&Bs[kb][cb*8 + 4]) = bp1;
        __syncthreads();
        if (k0 + 16 < K) {
            ap  = *(const float4*)(Aip + k0 + 16);
            bp0 = *(const float4*)(Bip + (size_t)(k0 + 16) * ldb);
            bp1 = *(const float4*)(Bip + (size_t)(k0 + 16) * ldb + 4);
        }
#pragma unroll
        for (int kk = 0; kk < 16; kk++) {
            float4 a4 = *(const float4*)(&As[kk][ty * 4]);
            ulonglong2 bb0 = *(const ulonglong2*)(&Bs[kk][tx * 8]);
            ulonglong2 bb1 = *(const ulonglong2*)(&Bs[kk][tx * 8 + 4]);
            ull ad[4] = {pack2(a4.x, a4.x), pack2(a4.y, a4.y),
                         pack2(a4.z, a4.z), pack2(a4.w, a4.w)};
#pragma unroll
            for (int i = 0; i < 4; i++) {
                fma2(acc2[i][0], ad[i], bb0.x);
                fma2(acc2[i][1], ad[i], bb0.y);
                fma2(acc2[i][2], ad[i], bb1.x);
                fma2(acc2[i][3], ad[i], bb1.y);
            }
        }
        __syncthreads();
    }
#pragma unroll
    for (int i = 0; i < 4; i++) {
        float2 p0 = unpack2(acc2[i][0]), p1 = unpack2(acc2[i][1]);
        float2 p2 = unpack2(acc2[i][2]), p3 = unpack2(acc2[i][3]);
        float* cp = C + (size_t)(m0 + ty * 4 + i) * INNER + n0 + tx * 8;
        *(float4*)cp       = make_float4(p0.x, p0.y, p1.x, p1.y);
        *(float4*)(cp + 4) = make_float4(p2.x, p2.y, p3.x, p3.y);
    }
}

// ---------------- attention (FFMA2 sim GEMM) ----------------
// grid (64, 14), 256 threads (16x16), 4x8 microtile. Dynamic smem.
__global__ void k_attn(const float* __restrict__ null_k, const int* __restrict__ mask,
                       float* __restrict__ out) {
    extern __shared__ float sm[];
    float (*Qs)[68]   = (float(*)[68])sm;                        // 64 x 68
    float (*Ks)[128]  = (float(*)[128])(sm + 64 * 68);           // 64 x 128
    float* vps        = sm + 64 * 68 + 64 * 128;                 // 128
    float* validS     = vps + 128;                               // 128
    float (*RedA)[17] = (float(*)[17])(validS + 128);            // 64 x 17
    float (*RedB)[17] = (float(*)[17])(validS + 128 + 64 * 17);  // 64 x 17
    float* rowmaxS    = validS + 128 + 2 * 64 * 17;              // 64
    float* rowacc     = rowmaxS + 64;                            // 64

    int c = blockIdx.x, n0 = blockIdx.y * 64;
    int t = threadIdx.x;
    int tx = t & 15, ty = t >> 4;

    if (t < 128) validS[t] = (t == 0 || mask[t - 1] != 0) ? 1.f : 0.f;
    if (t < 64)  rowacc[t] = 0.f;
    __syncthreads();

    float vj[8];
#pragma unroll
    for (int jj = 0; jj < 8; jj++) vj[jj] = validS[tx * 8 + jj];

    int rq = t >> 2, dq0 = (t & 3) * 4;     // Q loader
    int jk = t >> 1, dk0 = (t & 1) * 32;    // K loader
    const float* kp = (jk == 0) ? null_k
                                : g_k + ((size_t)(c * NJ + jk - 1)) * INNER;

    for (int h = 0; h < NH; h++) {
#pragma unroll
        for (int u = 0; u < 4; u++) {
            int d = dq0 + u * 16;
            float4 qv = *(const float4*)(g_q + (size_t)(n0 + rq) * INNER + h * HD + d);
            Qs[d][rq] = qv.x; Qs[d+1][rq] = qv.y; Qs[d+2][rq] = qv.z; Qs[d+3][rq] = qv.w;
        }
#pragma unroll
        for (int u = 0; u < 8; u++) {
            int d = dk0 + u * 4;
            float4 kv = *(const float4*)(kp + h * HD + d);
            Ks[d][jk] = kv.x; Ks[d+1][jk] = kv.y; Ks[d+2][jk] = kv.z; Ks[d+3][jk] = kv.w;
        }
        if (t < 128)
            vps[t] = (t == 0) ? g_vpnull[h] : g_vpt[((size_t)c * NH + h) * NJ + t - 1];
        __syncthreads();

        ull acc2[4][4];
#pragma unroll
        for (int i = 0; i < 4; i++)
#pragma unroll
            for (int jj = 0; jj < 4; jj++) acc2[i][jj] = 0ULL;
#pragma unroll 8
        for (int kk = 0; kk < 64; kk++) {
            float4 a4 = *(const float4*)(&Qs[kk][ty * 4]);
            ulonglong2 bb0 = *(const ulonglong2*)(&Ks[kk][tx * 8]);
            ulonglong2 bb1 = *(const ulonglong2*)(&Ks[kk][tx * 8 + 4]);
            ull ad[4] = {pack2(a4.x, a4.x), pack2(a4.y, a4.y),
                         pack2(a4.z, a4.z), pack2(a4.w, a4.w)};
#pragma unroll
            for (int i = 0; i < 4; i++) {
                fma2(acc2[i][0], ad[i], bb0.x);
                fma2(acc2[i][1], ad[i], bb0.y);
                fma2(acc2[i][2], ad[i], bb1.x);
                fma2(acc2[i][3], ad[i], bb1.y);
            }
        }

        float acc[4][8];
#pragma unroll
        for (int i = 0; i < 4; i++) {
            float2 p0 = unpack2(acc2[i][0]), p1 = unpack2(acc2[i][1]);
            float2 p2 = unpack2(acc2[i][2]), p3 = unpack2(acc2[i][3]);
            acc[i][0] = p0.x; acc[i][1] = p0.y; acc[i][2] = p1.x; acc[i][3] = p1.y;
            acc[i][4] = p2.x; acc[i][5] = p2.y; acc[i][6] = p3.x; acc[i][7] = p3.y;
        }

        float vpr[8];
#pragma unroll
        for (int jj = 0; jj < 8; jj++) vpr[jj] = vps[tx * 8 + jj];

#pragma unroll
        for (int i = 0; i < 4; i++) {
            float m = -1e30f;
#pragma unroll
            for (int jj = 0; jj < 8; jj++) {
                acc[i][jj] *= 0.125f;
                if (vj[jj] > 0.f) m = fmaxf(m, acc[i][jj]);
            }
            RedA[ty * 4 + i][tx] = m;
        }
        __syncthreads();
        if (t < 64) {
            float m = RedA[t][0];
#pragma unroll
            for (int k = 1; k < 16; k++) m = fmaxf(m, RedA[t][k]);
            rowmaxS[t] = m;
        }
        __syncthreads();
#pragma unroll
        for (int i = 0; i < 4; i++) {
            int r = ty * 4 + i;
            float rm = rowmaxS[r];
            float s = 0.f, tv = 0.f;
#pragma unroll
            for (int jj = 0; jj < 8; jj++) {
                float e = vj[jj] * __expf(acc[i][jj] - rm);
                s += e; tv += e * vpr[jj];
            }
            RedA[r][tx] = s; RedB[r][tx] = tv;
        }
        __syncthreads();
        if (t < 64) {
            float S = 0.f, T = 0.f;
#pragma unroll
            for (int k = 0; k < 16; k++) { S += RedA[t][k]; T += RedB[t][k]; }
            rowacc[t] += T / S;
        }
        __syncthreads();
    }
    if (t < 64) {
        int n = n0 + t;
        float x = g_ep[n] + g_bias + rowacc[t];
        out[(size_t)n * NC + c] = fmaxf(x, 0.f) + log1pf(__expf(-fabsf(x)));
    }
}

// ---------------- launch ----------------
extern "C" void kernel_launch(void* const* d_in, const int* in_sizes, int n_in,
                              void* d_out, int out_size) {
    const float* emb      = (const float*)d_in[0];
    const float* ctx      = (const float*)d_in[1];
    const int*   cmask    = (const int*)d_in[2];
    const float* q_gamma  = (const float*)d_in[3];
    const float* q_beta   = (const float*)d_in[4];
    const float* kv_gamma = (const float*)d_in[5];
    const float* kv_beta  = (const float*)d_in[6];
    const float* Wq       = (const float*)d_in[7];
    const float* Wkv      = (const float*)d_in[8];
    const float* null_k   = (const float*)d_in[9];
    const float* null_v   = (const float*)d_in[10];
    const float* Wo       = (const float*)d_in[11];
    const float* bo       = (const float*)d_in[12];
    const float* Wp       = (const float*)d_in[13];
    const float* bp       = (const float*)d_in[14];
    float* out = (float*)d_out;

    const int attn_smem = (64*68 + 64*128 + 128 + 128 + 2*64*17 + 64 + 64) * (int)sizeof(float);
    cudaFuncSetAttribute(k_attn, cudaFuncAttributeMaxDynamicSharedMemorySize, attn_smem);

    k_pre<<<N_SEQ + 512 + N_SEQ + 1, 256>>>(emb, q_gamma, q_beta, Wo, Wp, bo, bp);
    k_prep2<<<33, 256>>>(Wkv, null_v);
    k_ln_c<<<NC * NJ, 256>>>(ctx, kv_gamma, kv_beta);
    k_gemm_fused<<<508 + 56, 256>>>(Wq, Wkv);
    k_attn<<<dim3(NC, N_SEQ / 64), 256, attn_smem>>>(null_k, cmask, out);
}

// round 6
// speedup vs baseline: 2.3596x; 2.3596x over previous
#include <cuda_runtime.h>
#include <cuda_bf16.h>
#include <math.h>

#define N_SEQ 896
#define DH    3072
#define NC    64
#define NJ    127
#define DC    1024
#define INNER 512
#define NH    8
#define HD    64
#define MPAD  8192
#define AROW  40          // padded smem row (bf16 elements), 80B stride: conflict-free ldmatrix

// ---------------- scratch (static device memory; no allocations) ----------------
__device__ float g_w[INNER];
__device__ float g_ep[N_SEQ];
__device__ float g_bias;
__device__ float g_wvpt[NH * DC];
__device__ float g_vpnull[NH];
__device__ float g_lnq[(size_t)N_SEQ * DH];
__device__ float g_lnc[(size_t)MPAD * DC];
__device__ float g_q[(size_t)N_SEQ * INNER];
__device__ float g_k[(size_t)MPAD * INNER];
__device__ float g_vpt[NC * NH * NJ];
__device__ __nv_bfloat16 g_wk_hi[(size_t)INNER * DC];
__device__ __nv_bfloat16 g_wk_lo[(size_t)INNER * DC];
__device__ __nv_bfloat16 g_wq_hi[(size_t)INNER * DH];
__device__ __nv_bfloat16 g_wq_lo[(size_t)INNER * DH];

__device__ __forceinline__ float warpSum(float v) {
#pragma unroll
    for (int o = 16; o > 0; o >>= 1) v += __shfl_xor_sync(0xffffffffu, v, o);
    return v;
}
__device__ __forceinline__ unsigned b2u(__nv_bfloat162 h) {
    return *reinterpret_cast<unsigned*>(&h);
}
__device__ __forceinline__ unsigned smem_u32(const void* p) {
    unsigned a;
    asm("{ .reg .u64 t; cvta.to.shared.u64 t, %1; cvt.u32.u64 %0, t; }" : "=r"(a) : "l"(p));
    return a;
}
__device__ __forceinline__ void ldm_x4(unsigned* r, unsigned addr) {
    asm volatile("ldmatrix.sync.aligned.m8n8.x4.shared.b16 {%0,%1,%2,%3}, [%4];"
        : "=r"(r[0]), "=r"(r[1]), "=r"(r[2]), "=r"(r[3]) : "r"(addr));
}
__device__ __forceinline__ void ldm_x2(unsigned* r, unsigned addr) {
    asm volatile("ldmatrix.sync.aligned.m8n8.x2.shared.b16 {%0,%1}, [%2];"
        : "=r"(r[0]), "=r"(r[1]) : "r"(addr));
}
__device__ __forceinline__ void mma_bf16(float* d, const unsigned* a, const unsigned* b) {
    asm volatile("mma.sync.aligned.m16n8k16.row.col.f32.bf16.bf16.f32 "
        "{%0,%1,%2,%3}, {%4,%5,%6,%7}, {%8,%9}, {%0,%1,%2,%3};"
        : "+f"(d[0]), "+f"(d[1]), "+f"(d[2]), "+f"(d[3])
        : "r"(a[0]), "r"(a[1]), "r"(a[2]), "r"(a[3]), "r"(b[0]), "r"(b[1]));
}

// ---------------- fused pre-pass: LN(embeddings) + Wp dot products -----------
__global__ void k_pre(const float* __restrict__ emb, const float* __restrict__ gamma,
                      const float* __restrict__ beta, const float* __restrict__ Wo,
                      const float* __restrict__ Wp, const float* __restrict__ bo,
                      const float* __restrict__ bp) {
    __shared__ float row[DH];
    __shared__ float red[18];
    int bid = blockIdx.x, t = threadIdx.x;
    if (bid >= N_SEQ) {
        int id = bid - N_SEQ;
        const float* a;
        if (id < 512)            a = Wo  + (size_t)id * DH;
        else if (id < 512+N_SEQ) a = emb + (size_t)(id - 512) * DH;
        else                     a = bo;
        float s = 0.f;
        for (int i = t; i < DH; i += 256) s = fmaf(a[i], Wp[i], s);
        s = warpSum(s);
        if ((t & 31) == 0) red[t >> 5] = s;
        __syncthreads();
        if (t == 0) {
            float S = 0.f;
#pragma unroll
            for (int i = 0; i < 8; i++) S += red[i];
            if (id < 512)              g_w[id] = S;
            else if (id < 512 + N_SEQ) g_ep[id - 512] = S;
            else                       g_bias = S + bp[0];
        }
        return;
    }
    const float* xr = emb + (size_t)bid * DH;
    float s = 0.f, ss = 0.f;
#pragma unroll
    for (int u = 0; u < 3; u++) {
        int idx = (t + u * 256) * 4;
        float4 v = *(const float4*)(xr + idx);
        row[idx] = v.x; row[idx+1] = v.y; row[idx+2] = v.z; row[idx+3] = v.w;
        s  += v.x + v.y + v.z + v.w;
        ss += v.x*v.x + v.y*v.y + v.z*v.z + v.w*v.w;
    }
    s = warpSum(s); ss = warpSum(ss);
    if ((t & 31) == 0) { red[t >> 5] = s; red[8 + (t >> 5)] = ss; }
    __syncthreads();
    if (t == 0) {
        float S = 0.f, SS = 0.f;
#pragma unroll
        for (int i = 0; i < 8; i++) { S += red[i]; SS += red[8 + i]; }
        float mu = S / DH;
        float var = SS / DH - mu * mu;
        red[16] = mu; red[17] = rsqrtf(var + 1e-5f);
    }
    __syncthreads();
    float mu = red[16], rstd = red[17];
    float* outr = g_lnq + (size_t)bid * DH;
#pragma unroll
    for (int u = 0; u < 3; u++) {
        int idx = (t + u * 256) * 4;
        float4 o;
        o.x = (row[idx]   - mu) * rstd * gamma[idx]   + beta[idx];
        o.y = (row[idx+1] - mu) * rstd * gamma[idx+1] + beta[idx+1];
        o.z = (row[idx+2] - mu) * rstd * gamma[idx+2] + beta[idx+2];
        o.w = (row[idx+3] - mu) * rstd * gamma[idx+3] + beta[idx+3];
        *(float4*)(outr + idx) = o;
    }
}

// ---------------- prep 2: Wv_p^T and vp_null ----------------
__global__ void k_prep2(const float* __restrict__ Wkv, const float* __restrict__ null_v) {
    int bid = blockIdx.x, t = threadIdx.x;
    if (bid < 32) {
        int gid = bid * 256 + t;
        int h = gid >> 10, i = gid & 1023;
        const float* wrow = g_w + h * HD;
        const float* src  = Wkv + (size_t)i * (2 * INNER) + INNER + h * HD;
        float s = 0.f;
#pragma unroll
        for (int d = 0; d < HD; d++) s = fmaf(src[d], wrow[d], s);
        g_wvpt[h * DC + i] = s;
    } else if (t < NH) {
        float s = 0.f;
#pragma unroll
        for (int d = 0; d < HD; d++) s = fmaf(null_v[t * HD + d], g_w[t * HD + d], s);
        g_vpnull[t] = s;
    }
}

// ---------------- LN over context rows + fused vp; pads rows to 8192 -----
__global__ void k_ln_c(const float* __restrict__ x, const float* __restrict__ gamma,
                       const float* __restrict__ beta) {
    __shared__ float row[DC];
    __shared__ float red[18];
    int b = blockIdx.x, t = threadIdx.x;
    if (b >= NC * NJ) {
        *(float4*)(g_lnc + (size_t)b * DC + t * 4) = make_float4(0.f, 0.f, 0.f, 0.f);
        return;
    }
    const float* xr = x + (size_t)b * DC;
    int idx = t * 4;
    float4 v = *(const float4*)(xr + idx);
    float s  = v.x + v.y + v.z + v.w;
    float ss = v.x*v.x + v.y*v.y + v.z*v.z + v.w*v.w;
    s = warpSum(s); ss = warpSum(ss);
    if ((t & 31) == 0) { red[t >> 5] = s; red[8 + (t >> 5)] = ss; }
    __syncthreads();
    if (t == 0) {
        float S = 0.f, SS = 0.f;
#pragma unroll
        for (int i = 0; i < 8; i++) { S += red[i]; SS += red[8 + i]; }
        float mu = S / DC;
        float var = SS / DC - mu * mu;
        red[16] = mu; red[17] = rsqrtf(var + 1e-5f);
    }
    __syncthreads();
    float mu = red[16], rstd = red[17];
    float4 o;
    o.x = (v.x - mu) * rstd * gamma[idx]   + beta[idx];
    o.y = (v.y - mu) * rstd * gamma[idx+1] + beta[idx+1];
    o.z = (v.z - mu) * rstd * gamma[idx+2] + beta[idx+2];
    o.w = (v.w - mu) * rstd * gamma[idx+3] + beta[idx+3];
    *(float4*)(&row[idx]) = o;
    *(float4*)(g_lnc + (size_t)b * DC + idx) = o;
    __syncthreads();
    int w = t >> 5, lane = t & 31;
    const float* wv = g_wvpt + w * DC;
    float acc = 0.f;
#pragma unroll
    for (int m = 0; m < 32; m++) acc = fmaf(row[lane + 32 * m], wv[lane + 32 * m], acc);
    acc = warpSum(acc);
    if (lane == 0) {
        int c = b / NJ, j = b % NJ;
        g_vpt[((size_t)c * NH + w) * NJ + j] = acc;
    }
}

// ---------------- weight transpose + bf16 hi/lo split ----------------
__global__ void k_wconv(const float* __restrict__ src, __nv_bfloat16* __restrict__ dh,
                        __nv_bfloat16* __restrict__ dl, int K, int ldsrc) {
    __shared__ float tile[32][33];
    int tx = threadIdx.x, ty = threadIdx.y;
    int k0 = blockIdx.x * 32, n0 = blockIdx.y * 32;
#pragma unroll
    for (int r = 0; r < 4; r++)
        tile[ty + 8 * r][tx] = src[(size_t)(k0 + ty + 8 * r) * ldsrc + n0 + tx];
    __syncthreads();
#pragma unroll
    for (int r = 0; r < 4; r++) {
        int n = n0 + ty + 8 * r;
        float v = tile[tx][ty + 8 * r];
        __nv_bfloat16 h = __float2bfloat16_rn(v);
        __nv_bfloat16 l = __float2bfloat16_rn(v - __bfloat162float(h));
        dh[(size_t)n * K + k0 + tx] = h;
        dl[(size_t)n * K + k0 + tx] = l;
    }
}

// ---------------- HMMA GEMM: bf16 hi/lo split, 128x128 tile, BK=32 --------------
// bid < 256: k-proj (M=8192, K=1024); else q-proj (M=896, K=3072)
__global__ __launch_bounds__(256) void k_gemm_mma() {
    __shared__ __nv_bfloat16 Ah_s[128 * AROW], Al_s[128 * AROW];
    __shared__ __nv_bfloat16 Bh_s[128 * AROW], Bl_s[128 * AROW];

    int t = threadIdx.x, bid = blockIdx.x;
    const float* A; const __nv_bfloat16 *Bh, *Bl; float* C;
    int lda, Kb, m0, n0;
    if (bid < 256) {
        m0 = (bid >> 2) * 128; n0 = (bid & 3) * 128;
        A = g_lnc; lda = DC; Kb = DC; Bh = g_wk_hi; Bl = g_wk_lo; C = g_k;
    } else {
        int l = bid - 256;
        m0 = (l >> 2) * 128; n0 = (l & 3) * 128;
        A = g_lnq; lda = DH; Kb = DH; Bh = g_wq_hi; Bl = g_wq_lo; C = g_q;
    }
    int warp = t >> 5, lane = t & 31;
    int wm = (warp & 1) * 64, wn = (warp >> 1) * 32;

    float D[4][4][4];
#pragma unroll
    for (int i = 0; i < 4; i++)
#pragma unroll
        for (int j = 0; j < 4; j++)
#pragma unroll
            for (int k = 0; k < 4; k++) D[i][j][k] = 0.f;

    // staging: thread -> row t>>1, k-chunk (t&1)*16
    int srow = t >> 1, skc = (t & 1) * 16;
    const float* apg = A + (size_t)(m0 + srow) * lda + skc;
    const __nv_bfloat16* bhg = Bh + (size_t)(n0 + srow) * Kb + skc;
    const __nv_bfloat16* blg = Bl + (size_t)(n0 + srow) * Kb + skc;

    unsigned ah_b = smem_u32(Ah_s), al_b = smem_u32(Al_s);
    unsigned bh_b = smem_u32(Bh_s), bl_b = smem_u32(Bl_s);
    // ldmatrix per-lane offsets (bytes)
    unsigned aoff = (unsigned)(((lane & 15) * AROW + (lane >> 4) * 8) * 2);
    unsigned boff = (unsigned)((((lane & 15) & 7) * AROW + (((lane & 15) >> 3) & 1) * 8) * 2);

    for (int k0 = 0; k0 < Kb; k0 += 32) {
        // ---- stage A: fp32 -> hi/lo bf16 ----
#pragma unroll
        for (int u = 0; u < 4; u++) {
            float4 v = *(const float4*)(apg + k0 + u * 4);
            __nv_bfloat162 h01 = __float22bfloat162_rn(make_float2(v.x, v.y));
            __nv_bfloat162 h23 = __float22bfloat162_rn(make_float2(v.z, v.w));
            __nv_bfloat162 l01 = __float22bfloat162_rn(make_float2(
                v.x - __bfloat162float(h01.x), v.y - __bfloat162float(h01.y)));
            __nv_bfloat162 l23 = __float22bfloat162_rn(make_float2(
                v.z - __bfloat162float(h23.x), v.w - __bfloat162float(h23.y)));
            int e = srow * AROW + skc + u * 4;
            *(uint2*)(Ah_s + e) = make_uint2(b2u(h01), b2u(h23));
            *(uint2*)(Al_s + e) = make_uint2(b2u(l01), b2u(l23));
        }
        // ---- stage B: bf16 hi/lo copy ----
        {
            int e = srow * AROW + skc;
            *(uint4*)(Bh_s + e)     = *(const uint4*)(bhg + k0);
            *(uint4*)(Bh_s + e + 8) = *(const uint4*)(bhg + k0 + 8);
            *(uint4*)(Bl_s + e)     = *(const uint4*)(blg + k0);
            *(uint4*)(Bl_s + e + 8) = *(const uint4*)(blg + k0 + 8);
        }
        __syncthreads();
#pragma unroll
        for (int ks = 0; ks < 32; ks += 16) {
            unsigned ah[4][4], al[4][4], bh2[4][2], bl2[4][2];
#pragma unroll
            for (int mt = 0; mt < 4; mt++) {
                unsigned rowb = (unsigned)(((wm + mt * 16) * AROW + ks) * 2);
                ldm_x4(ah[mt], ah_b + rowb + aoff);
                ldm_x4(al[mt], al_b + rowb + aoff);
            }
#pragma unroll
            for (int nt = 0; nt < 4; nt++) {
                unsigned rowb = (unsigned)(((wn + nt * 8) * AROW + ks) * 2);
                ldm_x2(bh2[nt], bh_b + rowb + boff);
                ldm_x2(bl2[nt], bl_b + rowb + boff);
            }
#pragma unroll
            for (int mt = 0; mt < 4; mt++)
#pragma unroll
                for (int nt = 0; nt < 4; nt++) {
                    mma_bf16(D[mt][nt], ah[mt], bh2[nt]);
                    mma_bf16(D[mt][nt], al[mt], bh2[nt]);
                    mma_bf16(D[mt][nt], ah[mt], bl2[nt]);
                }
        }
        __syncthreads();
    }
    // ---- epilogue ----
#pragma unroll
    for (int mt = 0; mt < 4; mt++) {
        int r0 = m0 + wm + mt * 16 + (lane >> 2);
#pragma unroll
        for (int nt = 0; nt < 4; nt++) {
            int col = n0 + wn + nt * 8 + 2 * (lane & 3);
            *(float2*)(C + (size_t)r0 * INNER + col)       = make_float2(D[mt][nt][0], D[mt][nt][1]);
            *(float2*)(C + (size_t)(r0 + 8) * INNER + col) = make_float2(D[mt][nt][2], D[mt][nt][3]);
        }
    }
}

// ---------------- attention (R3 SIMT version) ----------------
__global__ void k_attn(const float* __restrict__ null_k, const int* __restrict__ mask,
                       float* __restrict__ out) {
    extern __shared__ float smf[];
    float (*Qs)[68]   = (float(*)[68])smf;
    float (*Ks)[128]  = (float(*)[128])(smf + 64 * 68);
    float* vps        = smf + 64 * 68 + 64 * 128;
    float* validS     = vps + 128;
    float (*RedA)[17] = (float(*)[17])(validS + 128);
    float (*RedB)[17] = (float(*)[17])(validS + 128 + 64 * 17);
    float* rowmaxS    = validS + 128 + 2 * 64 * 17;
    float* rowacc     = rowmaxS + 64;

    int c = blockIdx.x, n0 = blockIdx.y * 64;
    int t = threadIdx.x;
    int tx = t & 15, ty = t >> 4;

    if (t < 128) validS[t] = (t == 0 || mask[t - 1] != 0) ? 1.f : 0.f;
    if (t < 64)  rowacc[t] = 0.f;
    __syncthreads();

    float vj[8];
#pragma unroll
    for (int jj = 0; jj < 8; jj++) vj[jj] = validS[tx * 8 + jj];

    int rq = t >> 2, dq0 = (t & 3) * 4;
    int jk = t >> 1, dk0 = (t & 1) * 32;
    const float* kp = (jk == 0) ? null_k
                                : g_k + ((size_t)(c * NJ + jk - 1)) * INNER;

    for (int h = 0; h < NH; h++) {
#pragma unroll
        for (int u = 0; u < 4; u++) {
            int d = dq0 + u * 16;
            float4 qv = *(const float4*)(g_q + (size_t)(n0 + rq) * INNER + h * HD + d);
            Qs[d][rq] = qv.x; Qs[d+1][rq] = qv.y; Qs[d+2][rq] = qv.z; Qs[d+3][rq] = qv.w;
        }
#pragma unroll
        for (int u = 0; u < 8; u++) {
            int d = dk0 + u * 4;
            float4 kv = *(const float4*)(kp + h * HD + d);
            Ks[d][jk] = kv.x; Ks[d+1][jk] = kv.y; Ks[d+2][jk] = kv.z; Ks[d+3][jk] = kv.w;
        }
        if (t < 128)
            vps[t] = (t == 0) ? g_vpnull[h] : g_vpt[((size_t)c * NH + h) * NJ + t - 1];
        __syncthreads();

        float acc[4][8];
#pragma unroll
        for (int i = 0; i < 4; i++)
#pragma unroll
            for (int jj = 0; jj < 8; jj++) acc[i][jj] = 0.f;
#pragma unroll 8
        for (int kk = 0; kk < 64; kk++) {
            float4 a4 = *(const float4*)(&Qs[kk][ty * 4]);
            float4 b0 = *(const float4*)(&Ks[kk][tx * 8]);
            float4 b1 = *(const float4*)(&Ks[kk][tx * 8 + 4]);
            float ar[4] = {a4.x, a4.y, a4.z, a4.w};
            float br[8] = {b0.x, b0.y, b0.z, b0.w, b1.x, b1.y, b1.z, b1.w};
#pragma unroll
            for (int i = 0; i < 4; i++)
#pragma unroll
                for (int jj = 0; jj < 8; jj++) acc[i][jj] = fmaf(ar[i], br[jj], acc[i][jj]);
        }

        float vpr[8];
#pragma unroll
        for (int jj = 0; jj < 8; jj++) vpr[jj] = vps[tx * 8 + jj];

#pragma unroll
        for (int i = 0; i < 4; i++) {
            float m = -1e30f;
#pragma unroll
            for (int jj = 0; jj < 8; jj++) {
                acc[i][jj] *= 0.125f;
                if (vj[jj] > 0.f) m = fmaxf(m, acc[i][jj]);
            }
            RedA[ty * 4 + i][tx] = m;
        }
        __syncthreads();
        if (t < 64) {
            float m = RedA[t][0];
#pragma unroll
            for (int k = 1; k < 16; k++) m = fmaxf(m, RedA[t][k]);
            rowmaxS[t] = m;
        }
        __syncthreads();
#pragma unroll
        for (int i = 0; i < 4; i++) {
            int r = ty * 4 + i;
            float rm = rowmaxS[r];
            float s = 0.f, tv = 0.f;
#pragma unroll
            for (int jj = 0; jj < 8; jj++) {
                float e = vj[jj] * __expf(acc[i][jj] - rm);
                s += e; tv += e * vpr[jj];
            }
            RedA[r][tx] = s; RedB[r][tx] = tv;
        }
        __syncthreads();
        if (t < 64) {
            float S = 0.f, T = 0.f;
#pragma unroll
            for (int k = 0; k < 16; k++) { S += RedA[t][k]; T += RedB[t][k]; }
            rowacc[t] += T / S;
        }
        __syncthreads();
    }
    if (t < 64) {
        int n = n0 + t;
        float x = g_ep[n] + g_bias + rowacc[t];
        out[(size_t)n * NC + c] = fmaxf(x, 0.f) + log1pf(__expf(-fabsf(x)));
    }
}

// ---------------- launch ----------------
extern "C" void kernel_launch(void* const* d_in, const int* in_sizes, int n_in,
                              void* d_out, int out_size) {
    const float* emb      = (const float*)d_in[0];
    const float* ctx      = (const float*)d_in[1];
    const int*   cmask    = (const int*)d_in[2];
    const float* q_gamma  = (const float*)d_in[3];
    const float* q_beta   = (const float*)d_in[4];
    const float* kv_gamma = (const float*)d_in[5];
    const float* kv_beta  = (const float*)d_in[6];
    const float* Wq       = (const float*)d_in[7];
    const float* Wkv      = (const float*)d_in[8];
    const float* null_k   = (const float*)d_in[9];
    const float* null_v   = (const float*)d_in[10];
    const float* Wo       = (const float*)d_in[11];
    const float* bo       = (const float*)d_in[12];
    const float* Wp       = (const float*)d_in[13];
    const float* bp       = (const float*)d_in[14];
    float* out = (float*)d_out;

    void *p_wkh, *p_wkl, *p_wqh, *p_wql;
    cudaGetSymbolAddress(&p_wkh, g_wk_hi);
    cudaGetSymbolAddress(&p_wkl, g_wk_lo);
    cudaGetSymbolAddress(&p_wqh, g_wq_hi);
    cudaGetSymbolAddress(&p_wql, g_wq_lo);

    const int attn_smem = (64*68 + 64*128 + 128 + 128 + 2*64*17 + 64 + 64) * (int)sizeof(float);
    cudaFuncSetAttribute(k_attn, cudaFuncAttributeMaxDynamicSharedMemorySize, attn_smem);

    k_pre<<<N_SEQ + 512 + N_SEQ + 1, 256>>>(emb, q_gamma, q_beta, Wo, Wp, bo, bp);
    k_prep2<<<33, 256>>>(Wkv, null_v);
    k_ln_c<<<MPAD, 256>>>(ctx, kv_gamma, kv_beta);
    k_wconv<<<dim3(DC / 32, INNER / 32), dim3(32, 8)>>>(Wkv,
        (__nv_bfloat16*)p_wkh, (__nv_bfloat16*)p_wkl, DC, 2 * INNER);
    k_wconv<<<dim3(DH / 32, INNER / 32), dim3(32, 8)>>>(Wq,
        (__nv_bfloat16*)p_wqh, (__nv_bfloat16*)p_wql, DH, INNER);
    k_gemm_mma<<<256 + 28, 256>>>();
    k_attn<<<dim3(NC, N_SEQ / 64), 256, attn_smem>>>(null_k, cmask, out);
}

// round 7
// speedup vs baseline: 3.3891x; 1.4363x over previous
#include <cuda_runtime.h>
#include <cuda_bf16.h>
#include <math.h>

#define N_SEQ 896
#define DH    3072
#define NC    64
#define NJ    127
#define DC    1024
#define INNER 512
#define NH    8
#define HD    64
#define MPAD  8192
#define AROW  40          // gemm smem row pad (bf16), 80B stride
#define KROW  72          // attn smem row pad (bf16), 144B stride: conflict-free ldmatrix

// ---------------- scratch ----------------
__device__ float g_w[INNER];
__device__ float g_ep[N_SEQ];
__device__ float g_bias;
__device__ float g_wvpt[NH * DC];
__device__ float g_vpnull[NH];
__device__ float g_lnq[(size_t)N_SEQ * DH];
__device__ float g_lnc[(size_t)MPAD * DC];
__device__ float g_vpt[NC * NH * NJ];
__device__ __nv_bfloat16 g_wk_hi[(size_t)INNER * DC];
__device__ __nv_bfloat16 g_wk_lo[(size_t)INNER * DC];
__device__ __nv_bfloat16 g_wq_hi[(size_t)INNER * DH];
__device__ __nv_bfloat16 g_wq_lo[(size_t)INNER * DH];
// projections as bf16 hi/lo (written by GEMM epilogue)
__device__ __nv_bfloat16 g_q_hi[(size_t)N_SEQ * INNER];
__device__ __nv_bfloat16 g_q_lo[(size_t)N_SEQ * INNER];
__device__ __nv_bfloat16 g_k_hi[(size_t)MPAD * INNER];
__device__ __nv_bfloat16 g_k_lo[(size_t)MPAD * INNER];

__device__ __forceinline__ float warpSum(float v) {
#pragma unroll
    for (int o = 16; o > 0; o >>= 1) v += __shfl_xor_sync(0xffffffffu, v, o);
    return v;
}
__device__ __forceinline__ unsigned b2u(__nv_bfloat162 h) {
    return *reinterpret_cast<unsigned*>(&h);
}
__device__ __forceinline__ unsigned smem_u32(const void* p) {
    unsigned a;
    asm("{ .reg .u64 t; cvta.to.shared.u64 t, %1; cvt.u32.u64 %0, t; }" : "=r"(a) : "l"(p));
    return a;
}
__device__ __forceinline__ void ldm_x4(unsigned* r, unsigned addr) {
    asm volatile("ldmatrix.sync.aligned.m8n8.x4.shared.b16 {%0,%1,%2,%3}, [%4];"
        : "=r"(r[0]), "=r"(r[1]), "=r"(r[2]), "=r"(r[3]) : "r"(addr));
}
__device__ __forceinline__ void ldm_x2(unsigned* r, unsigned addr) {
    asm volatile("ldmatrix.sync.aligned.m8n8.x2.shared.b16 {%0,%1}, [%2];"
        : "=r"(r[0]), "=r"(r[1]) : "r"(addr));
}
__device__ __forceinline__ void mma_bf16(float* d, const unsigned* a, const unsigned* b) {
    asm volatile("mma.sync.aligned.m16n8k16.row.col.f32.bf16.bf16.f32 "
        "{%0,%1,%2,%3}, {%4,%5,%6,%7}, {%8,%9}, {%0,%1,%2,%3};"
        : "+f"(d[0]), "+f"(d[1]), "+f"(d[2]), "+f"(d[3])
        : "r"(a[0]), "r"(a[1]), "r"(a[2]), "r"(a[3]), "r"(b[0]), "r"(b[1]));
}

// ---------------- fused pre-pass: LN(embeddings) + Wp dot products -----------
__global__ void k_pre(const float* __restrict__ emb, const float* __restrict__ gamma,
                      const float* __restrict__ beta, const float* __restrict__ Wo,
                      const float* __restrict__ Wp, const float* __restrict__ bo,
                      const float* __restrict__ bp) {
    __shared__ float row[DH];
    __shared__ float red[18];
    int bid = blockIdx.x, t = threadIdx.x;
    if (bid >= N_SEQ) {
        int id = bid - N_SEQ;
        const float* a;
        if (id < 512)            a = Wo  + (size_t)id * DH;
        else if (id < 512+N_SEQ) a = emb + (size_t)(id - 512) * DH;
        else                     a = bo;
        float s = 0.f;
        for (int i = t; i < DH; i += 256) s = fmaf(a[i], Wp[i], s);
        s = warpSum(s);
        if ((t & 31) == 0) red[t >> 5] = s;
        __syncthreads();
        if (t == 0) {
            float S = 0.f;
#pragma unroll
            for (int i = 0; i < 8; i++) S += red[i];
            if (id < 512)              g_w[id] = S;
            else if (id < 512 + N_SEQ) g_ep[id - 512] = S;
            else                       g_bias = S + bp[0];
        }
        return;
    }
    const float* xr = emb + (size_t)bid * DH;
    float s = 0.f, ss = 0.f;
#pragma unroll
    for (int u = 0; u < 3; u++) {
        int idx = (t + u * 256) * 4;
        float4 v = *(const float4*)(xr + idx);
        row[idx] = v.x; row[idx+1] = v.y; row[idx+2] = v.z; row[idx+3] = v.w;
        s  += v.x + v.y + v.z + v.w;
        ss += v.x*v.x + v.y*v.y + v.z*v.z + v.w*v.w;
    }
    s = warpSum(s); ss = warpSum(ss);
    if ((t & 31) == 0) { red[t >> 5] = s; red[8 + (t >> 5)] = ss; }
    __syncthreads();
    if (t == 0) {
        float S = 0.f, SS = 0.f;
#pragma unroll
        for (int i = 0; i < 8; i++) { S += red[i]; SS += red[8 + i]; }
        float mu = S / DH;
        float var = SS / DH - mu * mu;
        red[16] = mu; red[17] = rsqrtf(var + 1e-5f);
    }
    __syncthreads();
    float mu = red[16], rstd = red[17];
    float* outr = g_lnq + (size_t)bid * DH;
#pragma unroll
    for (int u = 0; u < 3; u++) {
        int idx = (t + u * 256) * 4;
        float4 o;
        o.x = (row[idx]   - mu) * rstd * gamma[idx]   + beta[idx];
        o.y = (row[idx+1] - mu) * rstd * gamma[idx+1] + beta[idx+1];
        o.z = (row[idx+2] - mu) * rstd * gamma[idx+2] + beta[idx+2];
        o.w = (row[idx+3] - mu) * rstd * gamma[idx+3] + beta[idx+3];
        *(float4*)(outr + idx) = o;
    }
}

// ---------------- prep 2: Wv_p^T and vp_null ----------------
__global__ void k_prep2(const float* __restrict__ Wkv, const float* __restrict__ null_v) {
    int bid = blockIdx.x, t = threadIdx.x;
    if (bid < 32) {
        int gid = bid * 256 + t;
        int h = gid >> 10, i = gid & 1023;
        const float* wrow = g_w + h * HD;
        const float* src  = Wkv + (size_t)i * (2 * INNER) + INNER + h * HD;
        float s = 0.f;
#pragma unroll
        for (int d = 0; d < HD; d++) s = fmaf(src[d], wrow[d], s);
        g_wvpt[h * DC + i] = s;
    } else if (t < NH) {
        float s = 0.f;
#pragma unroll
        for (int d = 0; d < HD; d++) s = fmaf(null_v[t * HD + d], g_w[t * HD + d], s);
        g_vpnull[t] = s;
    }
}

// ---------------- LN over context rows + fused vp; pads rows to 8192 -----
__global__ void k_ln_c(const float* __restrict__ x, const float* __restrict__ gamma,
                       const float* __restrict__ beta) {
    __shared__ float row[DC];
    __shared__ float red[18];
    int b = blockIdx.x, t = threadIdx.x;
    if (b >= NC * NJ) {
        *(float4*)(g_lnc + (size_t)b * DC + t * 4) = make_float4(0.f, 0.f, 0.f, 0.f);
        return;
    }
    const float* xr = x + (size_t)b * DC;
    int idx = t * 4;
    float4 v = *(const float4*)(xr + idx);
    float s  = v.x + v.y + v.z + v.w;
    float ss = v.x*v.x + v.y*v.y + v.z*v.z + v.w*v.w;
    s = warpSum(s); ss = warpSum(ss);
    if ((t & 31) == 0) { red[t >> 5] = s; red[8 + (t >> 5)] = ss; }
    __syncthreads();
    if (t == 0) {
        float S = 0.f, SS = 0.f;
#pragma unroll
        for (int i = 0; i < 8; i++) { S += red[i]; SS += red[8 + i]; }
        float mu = S / DC;
        float var = SS / DC - mu * mu;
        red[16] = mu; red[17] = rsqrtf(var + 1e-5f);
    }
    __syncthreads();
    float mu = red[16], rstd = red[17];
    float4 o;
    o.x = (v.x - mu) * rstd * gamma[idx]   + beta[idx];
    o.y = (v.y - mu) * rstd * gamma[idx+1] + beta[idx+1];
    o.z = (v.z - mu) * rstd * gamma[idx+2] + beta[idx+2];
    o.w = (v.w - mu) * rstd * gamma[idx+3] + beta[idx+3];
    *(float4*)(&row[idx]) = o;
    *(float4*)(g_lnc + (size_t)b * DC + idx) = o;
    __syncthreads();
    int w = t >> 5, lane = t & 31;
    const float* wv = g_wvpt + w * DC;
    float acc = 0.f;
#pragma unroll
    for (int m = 0; m < 32; m++) acc = fmaf(row[lane + 32 * m], wv[lane + 32 * m], acc);
    acc = warpSum(acc);
    if (lane == 0) {
        int c = b / NJ, j = b % NJ;
        g_vpt[((size_t)c * NH + w) * NJ + j] = acc;
    }
}

// ---------------- weight transpose + bf16 hi/lo split ----------------
__global__ void k_wconv(const float* __restrict__ src, __nv_bfloat16* __restrict__ dh,
                        __nv_bfloat16* __restrict__ dl, int K, int ldsrc) {
    __shared__ float tile[32][33];
    int tx = threadIdx.x, ty = threadIdx.y;
    int k0 = blockIdx.x * 32, n0 = blockIdx.y * 32;
#pragma unroll
    for (int r = 0; r < 4; r++)
        tile[ty + 8 * r][tx] = src[(size_t)(k0 + ty + 8 * r) * ldsrc + n0 + tx];
    __syncthreads();
#pragma unroll
    for (int r = 0; r < 4; r++) {
        int n = n0 + ty + 8 * r;
        float v = tile[tx][ty + 8 * r];
        __nv_bfloat16 h = __float2bfloat16_rn(v);
        __nv_bfloat16 l = __float2bfloat16_rn(v - __bfloat162float(h));
        dh[(size_t)n * K + k0 + tx] = h;
        dl[(size_t)n * K + k0 + tx] = l;
    }
}

// ---------------- HMMA GEMM: bf16 hi/lo split; epilogue stores bf16 hi/lo ------
__global__ __launch_bounds__(256) void k_gemm_mma() {
    __shared__ __nv_bfloat16 Ah_s[128 * AROW], Al_s[128 * AROW];
    __shared__ __nv_bfloat16 Bh_s[128 * AROW], Bl_s[128 * AROW];

    int t = threadIdx.x, bid = blockIdx.x;
    const float* A; const __nv_bfloat16 *Bh, *Bl;
    __nv_bfloat16 *Chi, *Clo;
    int lda, Kb, m0, n0;
    if (bid < 256) {
        m0 = (bid >> 2) * 128; n0 = (bid & 3) * 128;
        A = g_lnc; lda = DC; Kb = DC; Bh = g_wk_hi; Bl = g_wk_lo;
        Chi = g_k_hi; Clo = g_k_lo;
    } else {
        int l = bid - 256;
        m0 = (l >> 2) * 128; n0 = (l & 3) * 128;
        A = g_lnq; lda = DH; Kb = DH; Bh = g_wq_hi; Bl = g_wq_lo;
        Chi = g_q_hi; Clo = g_q_lo;
    }
    int warp = t >> 5, lane = t & 31;
    int wm = (warp & 1) * 64, wn = (warp >> 1) * 32;

    float D[4][4][4];
#pragma unroll
    for (int i = 0; i < 4; i++)
#pragma unroll
        for (int j = 0; j < 4; j++)
#pragma unroll
            for (int k = 0; k < 4; k++) D[i][j][k] = 0.f;

    int srow = t >> 1, skc = (t & 1) * 16;
    const float* apg = A + (size_t)(m0 + srow) * lda + skc;
    const __nv_bfloat16* bhg = Bh + (size_t)(n0 + srow) * Kb + skc;
    const __nv_bfloat16* blg = Bl + (size_t)(n0 + srow) * Kb + skc;

    unsigned ah_b = smem_u32(Ah_s), al_b = smem_u32(Al_s);
    unsigned bh_b = smem_u32(Bh_s), bl_b = smem_u32(Bl_s);
    unsigned aoff = (unsigned)(((lane & 15) * AROW + (lane >> 4) * 8) * 2);
    unsigned boff = (unsigned)(((lane & 7) * AROW + ((lane >> 3) & 1) * 8) * 2);

    for (int k0 = 0; k0 < Kb; k0 += 32) {
#pragma unroll
        for (int u = 0; u < 4; u++) {
            float4 v = *(const float4*)(apg + k0 + u * 4);
            __nv_bfloat162 h01 = __float22bfloat162_rn(make_float2(v.x, v.y));
            __nv_bfloat162 h23 = __float22bfloat162_rn(make_float2(v.z, v.w));
            __nv_bfloat162 l01 = __float22bfloat162_rn(make_float2(
                v.x - __bfloat162float(h01.x), v.y - __bfloat162float(h01.y)));
            __nv_bfloat162 l23 = __float22bfloat162_rn(make_float2(
                v.z - __bfloat162float(h23.x), v.w - __bfloat162float(h23.y)));
            int e = srow * AROW + skc + u * 4;
            *(uint2*)(Ah_s + e) = make_uint2(b2u(h01), b2u(h23));
            *(uint2*)(Al_s + e) = make_uint2(b2u(l01), b2u(l23));
        }
        {
            int e = srow * AROW + skc;
            *(uint4*)(Bh_s + e)     = *(const uint4*)(bhg + k0);
            *(uint4*)(Bh_s + e + 8) = *(const uint4*)(bhg + k0 + 8);
            *(uint4*)(Bl_s + e)     = *(const uint4*)(blg + k0);
            *(uint4*)(Bl_s + e + 8) = *(const uint4*)(blg + k0 + 8);
        }
        __syncthreads();
#pragma unroll
        for (int ks = 0; ks < 32; ks += 16) {
            unsigned ah[4][4], al[4][4], bh2[4][2], bl2[4][2];
#pragma unroll
            for (int mt = 0; mt < 4; mt++) {
                unsigned rowb = (unsigned)(((wm + mt * 16) * AROW + ks) * 2);
                ldm_x4(ah[mt], ah_b + rowb + aoff);
                ldm_x4(al[mt], al_b + rowb + aoff);
            }
#pragma unroll
            for (int nt = 0; nt < 4; nt++) {
                unsigned rowb = (unsigned)(((wn + nt * 8) * AROW + ks) * 2);
                ldm_x2(bh2[nt], bh_b + rowb + boff);
                ldm_x2(bl2[nt], bl_b + rowb + boff);
            }
#pragma unroll
            for (int mt = 0; mt < 4; mt++)
#pragma unroll
                for (int nt = 0; nt < 4; nt++) {
                    mma_bf16(D[mt][nt], ah[mt], bh2[nt]);
                    mma_bf16(D[mt][nt], al[mt], bh2[nt]);
                    mma_bf16(D[mt][nt], ah[mt], bl2[nt]);
                }
        }
        __syncthreads();
    }
    // ---- epilogue: fp32 -> bf16 hi/lo ----
#pragma unroll
    for (int mt = 0; mt < 4; mt++) {
        int r0 = m0 + wm + mt * 16 + (lane >> 2);
#pragma unroll
        for (int nt = 0; nt < 4; nt++) {
            int col = n0 + wn + nt * 8 + 2 * (lane & 3);
#pragma unroll
            for (int half = 0; half < 2; half++) {
                float v0 = D[mt][nt][half * 2], v1 = D[mt][nt][half * 2 + 1];
                __nv_bfloat162 hh = __float22bfloat162_rn(make_float2(v0, v1));
                __nv_bfloat162 ll = __float22bfloat162_rn(make_float2(
                    v0 - __bfloat162float(hh.x), v1 - __bfloat162float(hh.y)));
                size_t off = (size_t)(r0 + half * 8) * INNER + col;
                *(unsigned*)(Chi + off) = b2u(hh);
                *(unsigned*)(Clo + off) = b2u(ll);
            }
        }
    }
}

// ---------------- attention via HMMA: 128 q-rows x 128 j per (c, n-tile) -------
__global__ __launch_bounds__(256) void k_attn_mma(const float* __restrict__ null_k,
                                                  const int* __restrict__ mask,
                                                  float* __restrict__ out) {
    extern __shared__ char smc[];
    __nv_bfloat16* Qh_s = (__nv_bfloat16*)smc;                     // 128*KROW
    __nv_bfloat16* Ql_s = Qh_s + 128 * KROW;
    __nv_bfloat16* Kh_s = Ql_s + 128 * KROW;
    __nv_bfloat16* Kl_s = Kh_s + 128 * KROW;
    float* validS = (float*)(Kl_s + 128 * KROW);                   // 128
    float* vps    = validS + 128;                                  // 128
    float* RedS   = vps + 128;                                     // 128*4
    float* RedT   = RedS + 512;                                    // 128*4

    int c = blockIdx.x, n0 = blockIdx.y * 128;
    int t = threadIdx.x;
    int warp = t >> 5, lane = t & 31;
    int wm = (warp & 1) * 64, wn = (warp >> 1) * 32;
    int wg = warp >> 1;

    if (t < 128) validS[t] = (t == 0 || mask[t - 1] != 0) ? 1.f : 0.f;
    float racc = 0.f;

    int srow = t >> 1, skc = (t & 1) * 32;
    const __nv_bfloat16* qh = g_q_hi + (size_t)(n0 + srow) * INNER + skc;
    const __nv_bfloat16* ql = g_q_lo + (size_t)(n0 + srow) * INNER + skc;
    const __nv_bfloat16* kh = g_k_hi + (size_t)(c * NJ + srow - 1) * INNER + skc;
    const __nv_bfloat16* kl = g_k_lo + (size_t)(c * NJ + srow - 1) * INNER + skc;

    unsigned qh_b = smem_u32(Qh_s), ql_b = smem_u32(Ql_s);
    unsigned kh_b = smem_u32(Kh_s), kl_b = smem_u32(Kl_s);
    unsigned aoff = (unsigned)(((lane & 15) * KROW + (lane >> 4) * 8) * 2);
    unsigned boff = (unsigned)(((lane & 7) * KROW + ((lane >> 3) & 1) * 8) * 2);

    for (int h = 0; h < NH; h++) {
        // ---- stage Q ----
        {
            int e = srow * KROW + skc;
            const uint4* s0 = (const uint4*)(qh + h * HD);
            const uint4* s1 = (const uint4*)(ql + h * HD);
            uint4* d0 = (uint4*)(Qh_s + e);
            uint4* d1 = (uint4*)(Ql_s + e);
#pragma unroll
            for (int u = 0; u < 4; u++) { d0[u] = s0[u]; d1[u] = s1[u]; }
        }
        // ---- stage K (row 0 = null token, fp32 split) ----
        if (srow == 0) {
#pragma unroll
            for (int u = 0; u < 32; u++) {
                float v = null_k[h * HD + skc + u];
                __nv_bfloat16 hb = __float2bfloat16_rn(v);
                Kh_s[skc + u] = hb;
                Kl_s[skc + u] = __float2bfloat16_rn(v - __bfloat162float(hb));
            }
        } else {
            int e = srow * KROW + skc;
            const uint4* s0 = (const uint4*)(kh + h * HD);
            const uint4* s1 = (const uint4*)(kl + h * HD);
            uint4* d0 = (uint4*)(Kh_s + e);
            uint4* d1 = (uint4*)(Kl_s + e);
#pragma unroll
            for (int u = 0; u < 4; u++) { d0[u] = s0[u]; d1[u] = s1[u]; }
        }
        if (t < 128)
            vps[t] = (t == 0) ? g_vpnull[h] : g_vpt[((size_t)c * NH + h) * NJ + t - 1];
        __syncthreads();

        // ---- sim = Q @ K^T (3-pass hi/lo) ----
        float D[4][4][4];
#pragma unroll
        for (int i = 0; i < 4; i++)
#pragma unroll
            for (int j = 0; j < 4; j++)
#pragma unroll
                for (int k = 0; k < 4; k++) D[i][j][k] = 0.f;
#pragma unroll
        for (int ks = 0; ks < 64; ks += 16) {
            unsigned ah[4][4], al[4][4], bh2[4][2], bl2[4][2];
#pragma unroll
            for (int mt = 0; mt < 4; mt++) {
                unsigned rowb = (unsigned)(((wm + mt * 16) * KROW + ks) * 2);
                ldm_x4(ah[mt], qh_b + rowb + aoff);
                ldm_x4(al[mt], ql_b + rowb + aoff);
            }
#pragma unroll
            for (int nt = 0; nt < 4; nt++) {
                unsigned rowb = (unsigned)(((wn + nt * 8) * KROW + ks) * 2);
                ldm_x2(bh2[nt], kh_b + rowb + boff);
                ldm_x2(bl2[nt], kl_b + rowb + boff);
            }
#pragma unroll
            for (int mt = 0; mt < 4; mt++)
#pragma unroll
                for (int nt = 0; nt < 4; nt++) {
                    mma_bf16(D[mt][nt], ah[mt], bh2[nt]);
                    mma_bf16(D[mt][nt], al[mt], bh2[nt]);
                    mma_bf16(D[mt][nt], ah[mt], bl2[nt]);
                }
        }

        // ---- exp + weighted row sums (no max subtraction: logits bounded) ----
        float rS[4][2], rT[4][2];
#pragma unroll
        for (int mt = 0; mt < 4; mt++) { rS[mt][0] = rS[mt][1] = rT[mt][0] = rT[mt][1] = 0.f; }
#pragma unroll
        for (int nt = 0; nt < 4; nt++) {
            int c0 = wn + nt * 8 + 2 * (lane & 3);
            float vl0 = validS[c0], vl1 = validS[c0 + 1];
            float vp0 = vps[c0],    vp1 = vps[c0 + 1];
#pragma unroll
            for (int mt = 0; mt < 4; mt++) {
                float e00 = vl0 * __expf(D[mt][nt][0] * 0.125f);
                float e01 = vl1 * __expf(D[mt][nt][1] * 0.125f);
                float e10 = vl0 * __expf(D[mt][nt][2] * 0.125f);
                float e11 = vl1 * __expf(D[mt][nt][3] * 0.125f);
                rS[mt][0] += e00 + e01;
                rT[mt][0] += e00 * vp0 + e01 * vp1;
                rS[mt][1] += e10 + e11;
                rT[mt][1] += e10 * vp0 + e11 * vp1;
            }
        }
        // reduce across the 4 lanes holding the same row (lane&3 varies)
#pragma unroll
        for (int mt = 0; mt < 4; mt++)
#pragma unroll
            for (int half = 0; half < 2; half++) {
                float s = rS[mt][half], tt = rT[mt][half];
                s  += __shfl_xor_sync(0xffffffffu, s, 1);
                s  += __shfl_xor_sync(0xffffffffu, s, 2);
                tt += __shfl_xor_sync(0xffffffffu, tt, 1);
                tt += __shfl_xor_sync(0xffffffffu, tt, 2);
                if ((lane & 3) == 0) {
                    int row = wm + mt * 16 + (lane >> 2) + half * 8;
                    RedS[row * 4 + wg] = s;
                    RedT[row * 4 + wg] = tt;
                }
            }
        __syncthreads();
        if (t < 128) {
            float S = RedS[t*4] + RedS[t*4+1] + RedS[t*4+2] + RedS[t*4+3];
            float T = RedT[t*4] + RedT[t*4+1] + RedT[t*4+2] + RedT[t*4+3];
            racc += T / S;
        }
        __syncthreads();
    }
    if (t < 128) {
        int n = n0 + t;
        float x = g_ep[n] + g_bias + racc;
        out[(size_t)n * NC + c] = fmaxf(x, 0.f) + log1pf(__expf(-fabsf(x)));
    }
}

// ---------------- launch ----------------
extern "C" void kernel_launch(void* const* d_in, const int* in_sizes, int n_in,
                              void* d_out, int out_size) {
    const float* emb      = (const float*)d_in[0];
    const float* ctx      = (const float*)d_in[1];
    const int*   cmask    = (const int*)d_in[2];
    const float* q_gamma  = (const float*)d_in[3];
    const float* q_beta   = (const float*)d_in[4];
    const float* kv_gamma = (const float*)d_in[5];
    const float* kv_beta  = (const float*)d_in[6];
    const float* Wq       = (const float*)d_in[7];
    const float* Wkv      = (const float*)d_in[8];
    const float* null_k   = (const float*)d_in[9];
    const float* null_v   = (const float*)d_in[10];
    const float* Wo       = (const float*)d_in[11];
    const float* bo       = (const float*)d_in[12];
    const float* Wp       = (const float*)d_in[13];
    const float* bp       = (const float*)d_in[14];
    float* out = (float*)d_out;

    void *p_wkh, *p_wkl, *p_wqh, *p_wql;
    cudaGetSymbolAddress(&p_wkh, g_wk_hi);
    cudaGetSymbolAddress(&p_wkl, g_wk_lo);
    cudaGetSymbolAddress(&p_wqh, g_wq_hi);
    cudaGetSymbolAddress(&p_wql, g_wq_lo);

    const int attn_smem = 4 * 128 * KROW * 2 + (128 + 128 + 512 + 512) * (int)sizeof(float);
    cudaFuncSetAttribute(k_attn_mma, cudaFuncAttributeMaxDynamicSharedMemorySize, attn_smem);

    k_pre<<<N_SEQ + 512 + N_SEQ + 1, 256>>>(emb, q_gamma, q_beta, Wo, Wp, bo, bp);
    k_prep2<<<33, 256>>>(Wkv, null_v);
    k_ln_c<<<MPAD, 256>>>(ctx, kv_gamma, kv_beta);
    k_wconv<<<dim3(DC / 32, INNER / 32), dim3(32, 8)>>>(Wkv,
        (__nv_bfloat16*)p_wkh, (__nv_bfloat16*)p_wkl, DC, 2 * INNER);
    k_wconv<<<dim3(DH / 32, INNER / 32), dim3(32, 8)>>>(Wq,
        (__nv_bfloat16*)p_wqh, (__nv_bfloat16*)p_wql, DH, INNER);
    k_gemm_mma<<<256 + 28, 256>>>();
    k_attn_mma<<<dim3(NC, N_SEQ / 128), 256, attn_smem>>>(null_k, cmask, out);
}

// round 8
// speedup vs baseline: 4.0102x; 1.1833x over previous
#include <cuda_runtime.h>
#include <cuda_bf16.h>
#include <math.h>

#define N_SEQ 896
#define DH    3072
#define NC    64
#define NJ    127
#define DC    1024
#define INNER 512
#define NH    8
#define HD    64
#define MPAD  8192
#define AROW  40
#define KROW  72

// ---------------- scratch ----------------
__device__ float g_w[INNER];
__device__ float g_ep[N_SEQ];
__device__ float g_bias;
__device__ float g_wvpt[NH * DC];
__device__ float g_vpnull[NH];
__device__ float g_lnq[(size_t)N_SEQ * DH];
__device__ float g_lnc[(size_t)MPAD * DC];
__device__ float g_vpt[NC * NH * NJ];
__device__ __nv_bfloat16 g_wk_hi[(size_t)INNER * DC];
__device__ __nv_bfloat16 g_wk_lo[(size_t)INNER * DC];
__device__ __nv_bfloat16 g_wq_hi[(size_t)INNER * DH];
__device__ __nv_bfloat16 g_wq_lo[(size_t)INNER * DH];
__device__ __nv_bfloat16 g_q_hi[(size_t)N_SEQ * INNER];
__device__ __nv_bfloat16 g_q_lo[(size_t)N_SEQ * INNER];
__device__ __nv_bfloat16 g_k_hi[(size_t)MPAD * INNER];
__device__ __nv_bfloat16 g_k_lo[(size_t)MPAD * INNER];

__device__ __forceinline__ float warpSum(float v) {
#pragma unroll
    for (int o = 16; o > 0; o >>= 1) v += __shfl_xor_sync(0xffffffffu, v, o);
    return v;
}
__device__ __forceinline__ unsigned b2u(__nv_bfloat162 h) {
    return *reinterpret_cast<unsigned*>(&h);
}
__device__ __forceinline__ unsigned smem_u32(const void* p) {
    unsigned a;
    asm("{ .reg .u64 t; cvta.to.shared.u64 t, %1; cvt.u32.u64 %0, t; }" : "=r"(a) : "l"(p));
    return a;
}
__device__ __forceinline__ void ldm_x4(unsigned* r, unsigned addr) {
    asm volatile("ldmatrix.sync.aligned.m8n8.x4.shared.b16 {%0,%1,%2,%3}, [%4];"
        : "=r"(r[0]), "=r"(r[1]), "=r"(r[2]), "=r"(r[3]) : "r"(addr));
}
__device__ __forceinline__ void ldm_x2(unsigned* r, unsigned addr) {
    asm volatile("ldmatrix.sync.aligned.m8n8.x2.shared.b16 {%0,%1}, [%2];"
        : "=r"(r[0]), "=r"(r[1]) : "r"(addr));
}
__device__ __forceinline__ void mma_bf16(float* d, const unsigned* a, const unsigned* b) {
    asm volatile("mma.sync.aligned.m16n8k16.row.col.f32.bf16.bf16.f32 "
        "{%0,%1,%2,%3}, {%4,%5,%6,%7}, {%8,%9}, {%0,%1,%2,%3};"
        : "+f"(d[0]), "+f"(d[1]), "+f"(d[2]), "+f"(d[3])
        : "r"(a[0]), "r"(a[1]), "r"(a[2]), "r"(a[3]), "r"(b[0]), "r"(b[1]));
}

// ---------------- mega prologue --------------------------------------------
// [0,896): LN(emb row) -> g_lnq  AND  g_ep[row] = emb_row . Wp (fused)
// [896,1408): g_w[id] = Wo row . Wp ; 1408: bias
// [1409,1921): wconv Wkv->wk ; [1921,3457): wconv Wq->wq
__global__ void k_mega1(const float* __restrict__ emb, const float* __restrict__ gamma,
                        const float* __restrict__ beta, const float* __restrict__ Wo,
                        const float* __restrict__ Wp, const float* __restrict__ bo,
                        const float* __restrict__ bp, const float* __restrict__ Wkv,
                        const float* __restrict__ Wq) {
    __shared__ float row[DH];
    __shared__ float red[26];
    int bid = blockIdx.x, t = threadIdx.x;

    if (bid < N_SEQ) {
        // ---- LN + ep fused ----
        const float* xr = emb + (size_t)bid * DH;
        float s = 0.f, ss = 0.f, se = 0.f;
#pragma unroll
        for (int u = 0; u < 3; u++) {
            int idx = (t + u * 256) * 4;
            float4 v = *(const float4*)(xr + idx);
            float4 w = *(const float4*)(Wp + idx);
            row[idx] = v.x; row[idx+1] = v.y; row[idx+2] = v.z; row[idx+3] = v.w;
            s  += v.x + v.y + v.z + v.w;
            ss += v.x*v.x + v.y*v.y + v.z*v.z + v.w*v.w;
            se += v.x*w.x + v.y*w.y + v.z*w.z + v.w*w.w;
        }
        s = warpSum(s); ss = warpSum(ss); se = warpSum(se);
        if ((t & 31) == 0) { int w8 = t >> 5; red[w8] = s; red[8+w8] = ss; red[16+w8] = se; }
        __syncthreads();
        if (t == 0) {
            float S = 0.f, SS = 0.f, SE = 0.f;
#pragma unroll
            for (int i = 0; i < 8; i++) { S += red[i]; SS += red[8+i]; SE += red[16+i]; }
            float mu = S / DH;
            float var = SS / DH - mu * mu;
            red[24] = mu; red[25] = rsqrtf(var + 1e-5f);
            g_ep[bid] = SE;
        }
        __syncthreads();
        float mu = red[24], rstd = red[25];
        float* outr = g_lnq + (size_t)bid * DH;
#pragma unroll
        for (int u = 0; u < 3; u++) {
            int idx = (t + u * 256) * 4;
            float4 o;
            o.x = (row[idx]   - mu) * rstd * gamma[idx]   + beta[idx];
            o.y = (row[idx+1] - mu) * rstd * gamma[idx+1] + beta[idx+1];
            o.z = (row[idx+2] - mu) * rstd * gamma[idx+2] + beta[idx+2];
            o.w = (row[idx+3] - mu) * rstd * gamma[idx+3] + beta[idx+3];
            *(float4*)(outr + idx) = o;
        }
        return;
    }
    if (bid < 1409) {
        // ---- dot blocks: g_w rows, bias ----
        int id = bid - N_SEQ;
        const float* a = (id < 512) ? (Wo + (size_t)id * DH) : bo;
        float s = 0.f;
        for (int i = t; i < DH; i += 256) s = fmaf(a[i], Wp[i], s);
        s = warpSum(s);
        if ((t & 31) == 0) red[t >> 5] = s;
        __syncthreads();
        if (t == 0) {
            float S = 0.f;
#pragma unroll
            for (int i = 0; i < 8; i++) S += red[i];
            if (id < 512) g_w[id] = S;
            else          g_bias = S + bp[0];
        }
        return;
    }
    // ---- weight transpose + hi/lo split ----
    {
        float (*tile)[33] = (float(*)[33])row;
        const float* src; __nv_bfloat16 *dh, *dl;
        int K, ldsrc, k0, n0;
        if (bid < 1921) {
            int l = bid - 1409;
            K = DC; ldsrc = 2 * INNER; src = Wkv; dh = g_wk_hi; dl = g_wk_lo;
            k0 = (l & 31) * 32; n0 = (l >> 5) * 32;
        } else {
            int l = bid - 1921;
            K = DH; ldsrc = INNER; src = Wq; dh = g_wq_hi; dl = g_wq_lo;
            k0 = (l % 96) * 32; n0 = (l / 96) * 32;
        }
        int tx = t & 31, ty = t >> 5;
#pragma unroll
        for (int r = 0; r < 4; r++)
            tile[ty + 8 * r][tx] = src[(size_t)(k0 + ty + 8 * r) * ldsrc + n0 + tx];
        __syncthreads();
#pragma unroll
        for (int r = 0; r < 4; r++) {
            int n = n0 + ty + 8 * r;
            float v = tile[tx][ty + 8 * r];
            __nv_bfloat16 h = __float2bfloat16_rn(v);
            __nv_bfloat16 l2 = __float2bfloat16_rn(v - __bfloat162float(h));
            dh[(size_t)n * K + k0 + tx] = h;
            dl[(size_t)n * K + k0 + tx] = l2;
        }
    }
}

// ---------------- prep 2: Wv_p^T and vp_null ----------------
__global__ void k_prep2(const float* __restrict__ Wkv, const float* __restrict__ null_v) {
    int bid = blockIdx.x, t = threadIdx.x;
    if (bid < 32) {
        int gid = bid * 256 + t;
        int h = gid >> 10, i = gid & 1023;
        const float* wrow = g_w + h * HD;
        const float* src  = Wkv + (size_t)i * (2 * INNER) + INNER + h * HD;
        float s = 0.f;
#pragma unroll
        for (int d = 0; d < HD; d++) s = fmaf(src[d], wrow[d], s);
        g_wvpt[h * DC + i] = s;
    } else if (t < NH) {
        float s = 0.f;
#pragma unroll
        for (int d = 0; d < HD; d++) s = fmaf(null_v[t * HD + d], g_w[t * HD + d], s);
        g_vpnull[t] = s;
    }
}

// ---------------- LN over context rows: warp-per-row (8 rows/block) ----------
__global__ __launch_bounds__(256) void k_ln_c(const float* __restrict__ x,
                                              const float* __restrict__ gamma,
                                              const float* __restrict__ beta) {
    __shared__ float wvs[NH * DC];     // 32 KB
    int t = threadIdx.x, warp = t >> 5, lane = t & 31;
    for (int i = t; i < NH * DC; i += 256) wvs[i] = g_wvpt[i];
    __syncthreads();

    int b = blockIdx.x * 8 + warp;
    if (b >= NC * NJ) {
        if (b < MPAD) {
            float4 z = make_float4(0.f, 0.f, 0.f, 0.f);
#pragma unroll
            for (int c = 0; c < 8; c++)
                *(float4*)(g_lnc + (size_t)b * DC + c * 128 + lane * 4) = z;
        }
        return;
    }
    const float* xr = x + (size_t)b * DC;
    float4 r[8];
    float s = 0.f, ss = 0.f;
#pragma unroll
    for (int c = 0; c < 8; c++) {
        r[c] = *(const float4*)(xr + c * 128 + lane * 4);
        s  += r[c].x + r[c].y + r[c].z + r[c].w;
        ss += r[c].x*r[c].x + r[c].y*r[c].y + r[c].z*r[c].z + r[c].w*r[c].w;
    }
    s = warpSum(s); ss = warpSum(ss);
    float mu = s / DC;
    float rstd = rsqrtf(ss / DC - mu * mu + 1e-5f);
#pragma unroll
    for (int c = 0; c < 8; c++) {
        int idx = c * 128 + lane * 4;
        float4 g = *(const float4*)(gamma + idx);
        float4 bb = *(const float4*)(beta + idx);
        r[c].x = (r[c].x - mu) * rstd * g.x + bb.x;
        r[c].y = (r[c].y - mu) * rstd * g.y + bb.y;
        r[c].z = (r[c].z - mu) * rstd * g.z + bb.z;
        r[c].w = (r[c].w - mu) * rstd * g.w + bb.w;
        *(float4*)(g_lnc + (size_t)b * DC + idx) = r[c];
    }
    int cc = b / NJ, j = b % NJ;
#pragma unroll
    for (int h = 0; h < NH; h++) {
        float acc = 0.f;
#pragma unroll
        for (int c = 0; c < 8; c++) {
            int idx = h * DC + c * 128 + lane * 4;
            acc = fmaf(r[c].x, wvs[idx],   acc);
            acc = fmaf(r[c].y, wvs[idx+1], acc);
            acc = fmaf(r[c].z, wvs[idx+2], acc);
            acc = fmaf(r[c].w, wvs[idx+3], acc);
        }
        acc = warpSum(acc);
        if (lane == 0) g_vpt[((size_t)cc * NH + h) * NJ + j] = acc;
    }
}

// ---------------- HMMA GEMM with register double-buffering ----------------
__global__ __launch_bounds__(256) void k_gemm_mma() {
    __shared__ __nv_bfloat16 Ah_s[128 * AROW], Al_s[128 * AROW];
    __shared__ __nv_bfloat16 Bh_s[128 * AROW], Bl_s[128 * AROW];

    int t = threadIdx.x, bid = blockIdx.x;
    const float* A; const __nv_bfloat16 *Bh, *Bl;
    __nv_bfloat16 *Chi, *Clo;
    int lda, Kb, m0, n0;
    if (bid < 256) {
        m0 = (bid >> 2) * 128; n0 = (bid & 3) * 128;
        A = g_lnc; lda = DC; Kb = DC; Bh = g_wk_hi; Bl = g_wk_lo;
        Chi = g_k_hi; Clo = g_k_lo;
    } else {
        int l = bid - 256;
        m0 = (l >> 2) * 128; n0 = (l & 3) * 128;
        A = g_lnq; lda = DH; Kb = DH; Bh = g_wq_hi; Bl = g_wq_lo;
        Chi = g_q_hi; Clo = g_q_lo;
    }
    int warp = t >> 5, lane = t & 31;
    int wm = (warp & 1) * 64, wn = (warp >> 1) * 32;

    float D[4][4][4];
#pragma unroll
    for (int i = 0; i < 4; i++)
#pragma unroll
        for (int j = 0; j < 4; j++)
#pragma unroll
            for (int k = 0; k < 4; k++) D[i][j][k] = 0.f;

    int srow = t >> 1, skc = (t & 1) * 16;
    const float* apg = A + (size_t)(m0 + srow) * lda + skc;
    const __nv_bfloat16* bhg = Bh + (size_t)(n0 + srow) * Kb + skc;
    const __nv_bfloat16* blg = Bl + (size_t)(n0 + srow) * Kb + skc;

    unsigned ah_b = smem_u32(Ah_s), al_b = smem_u32(Al_s);
    unsigned bh_b = smem_u32(Bh_s), bl_b = smem_u32(Bl_s);
    unsigned aoff = (unsigned)(((lane & 15) * AROW + (lane >> 4) * 8) * 2);
    unsigned boff = (unsigned)(((lane & 7) * AROW + ((lane >> 3) & 1) * 8) * 2);

    // register prefetch buffers
    float4 av[4]; uint4 rbh[2], rbl[2];
#pragma unroll
    for (int u = 0; u < 4; u++) av[u] = *(const float4*)(apg + u * 4);
    rbh[0] = *(const uint4*)bhg; rbh[1] = *(const uint4*)(bhg + 8);
    rbl[0] = *(const uint4*)blg; rbl[1] = *(const uint4*)(blg + 8);

    for (int k0 = 0; k0 < Kb; k0 += 32) {
        // ---- store staged regs -> smem ----
#pragma unroll
        for (int u = 0; u < 4; u++) {
            float4 v = av[u];
            __nv_bfloat162 h01 = __float22bfloat162_rn(make_float2(v.x, v.y));
            __nv_bfloat162 h23 = __float22bfloat162_rn(make_float2(v.z, v.w));
            __nv_bfloat162 l01 = __float22bfloat162_rn(make_float2(
                v.x - __bfloat162float(h01.x), v.y - __bfloat162float(h01.y)));
            __nv_bfloat162 l23 = __float22bfloat162_rn(make_float2(
                v.z - __bfloat162float(h23.x), v.w - __bfloat162float(h23.y)));
            int e = srow * AROW + skc + u * 4;
            *(uint2*)(Ah_s + e) = make_uint2(b2u(h01), b2u(h23));
            *(uint2*)(Al_s + e) = make_uint2(b2u(l01), b2u(l23));
        }
        {
            int e = srow * AROW + skc;
            *(uint4*)(Bh_s + e)     = rbh[0];
            *(uint4*)(Bh_s + e + 8) = rbh[1];
            *(uint4*)(Bl_s + e)     = rbl[0];
            *(uint4*)(Bl_s + e + 8) = rbl[1];
        }
        __syncthreads();
        // ---- prefetch next slab (overlaps MMA) ----
        if (k0 + 32 < Kb) {
#pragma unroll
            for (int u = 0; u < 4; u++) av[u] = *(const float4*)(apg + k0 + 32 + u * 4);
            rbh[0] = *(const uint4*)(bhg + k0 + 32); rbh[1] = *(const uint4*)(bhg + k0 + 40);
            rbl[0] = *(const uint4*)(blg + k0 + 32); rbl[1] = *(const uint4*)(blg + k0 + 40);
        }
#pragma unroll
        for (int ks = 0; ks < 32; ks += 16) {
            unsigned ah[4][4], al[4][4], bh2[4][2], bl2[4][2];
#pragma unroll
            for (int mt = 0; mt < 4; mt++) {
                unsigned rowb = (unsigned)(((wm + mt * 16) * AROW + ks) * 2);
                ldm_x4(ah[mt], ah_b + rowb + aoff);
                ldm_x4(al[mt], al_b + rowb + aoff);
            }
#pragma unroll
            for (int nt = 0; nt < 4; nt++) {
                unsigned rowb = (unsigned)(((wn + nt * 8) * AROW + ks) * 2);
                ldm_x2(bh2[nt], bh_b + rowb + boff);
                ldm_x2(bl2[nt], bl_b + rowb + boff);
            }
#pragma unroll
            for (int mt = 0; mt < 4; mt++)
#pragma unroll
                for (int nt = 0; nt < 4; nt++) {
                    mma_bf16(D[mt][nt], ah[mt], bh2[nt]);
                    mma_bf16(D[mt][nt], al[mt], bh2[nt]);
                    mma_bf16(D[mt][nt], ah[mt], bl2[nt]);
                }
        }
        __syncthreads();
    }
    // ---- epilogue: fp32 -> bf16 hi/lo ----
#pragma unroll
    for (int mt = 0; mt < 4; mt++) {
        int r0 = m0 + wm + mt * 16 + (lane >> 2);
#pragma unroll
        for (int nt = 0; nt < 4; nt++) {
            int col = n0 + wn + nt * 8 + 2 * (lane & 3);
#pragma unroll
            for (int half = 0; half < 2; half++) {
                float v0 = D[mt][nt][half * 2], v1 = D[mt][nt][half * 2 + 1];
                __nv_bfloat162 hh = __float22bfloat162_rn(make_float2(v0, v1));
                __nv_bfloat162 ll = __float22bfloat162_rn(make_float2(
                    v0 - __bfloat162float(hh.x), v1 - __bfloat162float(hh.y)));
                size_t off = (size_t)(r0 + half * 8) * INNER + col;
                *(unsigned*)(Chi + off) = b2u(hh);
                *(unsigned*)(Clo + off) = b2u(ll);
            }
        }
    }
}

// ---------------- attention via HMMA ----------------
__global__ __launch_bounds__(256) void k_attn_mma(const float* __restrict__ null_k,
                                                  const int* __restrict__ mask,
                                                  float* __restrict__ out) {
    extern __shared__ char smc[];
    __nv_bfloat16* Qh_s = (__nv_bfloat16*)smc;
    __nv_bfloat16* Ql_s = Qh_s + 128 * KROW;
    __nv_bfloat16* Kh_s = Ql_s + 128 * KROW;
    __nv_bfloat16* Kl_s = Kh_s + 128 * KROW;
    float* validS = (float*)(Kl_s + 128 * KROW);
    float* vps    = validS + 128;
    float* RedS   = vps + 128;
    float* RedT   = RedS + 512;

    int c = blockIdx.x, n0 = blockIdx.y * 128;
    int t = threadIdx.x;
    int warp = t >> 5, lane = t & 31;
    int wm = (warp & 1) * 64, wn = (warp >> 1) * 32;
    int wg = warp >> 1;

    if (t < 128) validS[t] = (t == 0 || mask[t - 1] != 0) ? 1.f : 0.f;
    float racc = 0.f;

    int srow = t >> 1, skc = (t & 1) * 32;
    const __nv_bfloat16* qh = g_q_hi + (size_t)(n0 + srow) * INNER + skc;
    const __nv_bfloat16* ql = g_q_lo + (size_t)(n0 + srow) * INNER + skc;
    const __nv_bfloat16* kh = g_k_hi + (size_t)(c * NJ + srow - 1) * INNER + skc;
    const __nv_bfloat16* kl = g_k_lo + (size_t)(c * NJ + srow - 1) * INNER + skc;

    unsigned qh_b = smem_u32(Qh_s), ql_b = smem_u32(Ql_s);
    unsigned kh_b = smem_u32(Kh_s), kl_b = smem_u32(Kl_s);
    unsigned aoff = (unsigned)(((lane & 15) * KROW + (lane >> 4) * 8) * 2);
    unsigned boff = (unsigned)(((lane & 7) * KROW + ((lane >> 3) & 1) * 8) * 2);

    for (int h = 0; h < NH; h++) {
        {
            int e = srow * KROW + skc;
            const uint4* s0 = (const uint4*)(qh + h * HD);
            const uint4* s1 = (const uint4*)(ql + h * HD);
            uint4* d0 = (uint4*)(Qh_s + e);
            uint4* d1 = (uint4*)(Ql_s + e);
#pragma unroll
            for (int u = 0; u < 4; u++) { d0[u] = s0[u]; d1[u] = s1[u]; }
        }
        if (srow == 0) {
#pragma unroll
            for (int u = 0; u < 32; u++) {
                float v = null_k[h * HD + skc + u];
                __nv_bfloat16 hb = __float2bfloat16_rn(v);
                Kh_s[skc + u] = hb;
                Kl_s[skc + u] = __float2bfloat16_rn(v - __bfloat162float(hb));
            }
        } else {
            int e = srow * KROW + skc;
            const uint4* s0 = (const uint4*)(kh + h * HD);
            const uint4* s1 = (const uint4*)(kl + h * HD);
            uint4* d0 = (uint4*)(Kh_s + e);
            uint4* d1 = (uint4*)(Kl_s + e);
#pragma unroll
            for (int u = 0; u < 4; u++) { d0[u] = s0[u]; d1[u] = s1[u]; }
        }
        if (t < 128)
            vps[t] = (t == 0) ? g_vpnull[h] : g_vpt[((size_t)c * NH + h) * NJ + t - 1];
        __syncthreads();

        float D[4][4][4];
#pragma unroll
        for (int i = 0; i < 4; i++)
#pragma unroll
            for (int j = 0; j < 4; j++)
#pragma unroll
                for (int k = 0; k < 4; k++) D[i][j][k] = 0.f;
#pragma unroll
        for (int ks = 0; ks < 64; ks += 16) {
            unsigned ah[4][4], al[4][4], bh2[4][2], bl2[4][2];
#pragma unroll
            for (int mt = 0; mt < 4; mt++) {
                unsigned rowb = (unsigned)(((wm + mt * 16) * KROW + ks) * 2);
                ldm_x4(ah[mt], qh_b + rowb + aoff);
                ldm_x4(al[mt], ql_b + rowb + aoff);
            }
#pragma unroll
            for (int nt = 0; nt < 4; nt++) {
                unsigned rowb = (unsigned)(((wn + nt * 8) * KROW + ks) * 2);
                ldm_x2(bh2[nt], kh_b + rowb + boff);
                ldm_x2(bl2[nt], kl_b + rowb + boff);
            }
#pragma unroll
            for (int mt = 0; mt < 4; mt++)
#pragma unroll
                for (int nt = 0; nt < 4; nt++) {
                    mma_bf16(D[mt][nt], ah[mt], bh2[nt]);
                    mma_bf16(D[mt][nt], al[mt], bh2[nt]);
                    mma_bf16(D[mt][nt], ah[mt], bl2[nt]);
                }
        }

        float rS[4][2], rT[4][2];
#pragma unroll
        for (int mt = 0; mt < 4; mt++) { rS[mt][0] = rS[mt][1] = rT[mt][0] = rT[mt][1] = 0.f; }
#pragma unroll
        for (int nt = 0; nt < 4; nt++) {
            int c0 = wn + nt * 8 + 2 * (lane & 3);
            float vl0 = validS[c0], vl1 = validS[c0 + 1];
            float vp0 = vps[c0],    vp1 = vps[c0 + 1];
#pragma unroll
            for (int mt = 0; mt < 4; mt++) {
                float e00 = vl0 * __expf(D[mt][nt][0] * 0.125f);
                float e01 = vl1 * __expf(D[mt][nt][1] * 0.125f);
                float e10 = vl0 * __expf(D[mt][nt][2] * 0.125f);
                float e11 = vl1 * __expf(D[mt][nt][3] * 0.125f);
                rS[mt][0] += e00 + e01;
                rT[mt][0] += e00 * vp0 + e01 * vp1;
                rS[mt][1] += e10 + e11;
                rT[mt][1] += e10 * vp0 + e11 * vp1;
            }
        }
#pragma unroll
        for (int mt = 0; mt < 4; mt++)
#pragma unroll
            for (int half = 0; half < 2; half++) {
                float s = rS[mt][half], tt = rT[mt][half];
                s  += __shfl_xor_sync(0xffffffffu, s, 1);
                s  += __shfl_xor_sync(0xffffffffu, s, 2);
                tt += __shfl_xor_sync(0xffffffffu, tt, 1);
                tt += __shfl_xor_sync(0xffffffffu, tt, 2);
                if ((lane & 3) == 0) {
                    int row = wm + mt * 16 + (lane >> 2) + half * 8;
                    RedS[row * 4 + wg] = s;
                    RedT[row * 4 + wg] = tt;
                }
            }
        __syncthreads();
        if (t < 128) {
            float S = RedS[t*4] + RedS[t*4+1] + RedS[t*4+2] + RedS[t*4+3];
            float T = RedT[t*4] + RedT[t*4+1] + RedT[t*4+2] + RedT[t*4+3];
            racc += T / S;
        }
        __syncthreads();
    }
    if (t < 128) {
        int n = n0 + t;
        float x = g_ep[n] + g_bias + racc;
        out[(size_t)n * NC + c] = fmaxf(x, 0.f) + log1pf(__expf(-fabsf(x)));
    }
}

// ---------------- launch ----------------
extern "C" void kernel_launch(void* const* d_in, const int* in_sizes, int n_in,
                              void* d_out, int out_size) {
    const float* emb      = (const float*)d_in[0];
    const float* ctx      = (const float*)d_in[1];
    const int*   cmask    = (const int*)d_in[2];
    const float* q_gamma  = (const float*)d_in[3];
    const float* q_beta   = (const float*)d_in[4];
    const float* kv_gamma = (const float*)d_in[5];
    const float* kv_beta  = (const float*)d_in[6];
    const float* Wq       = (const float*)d_in[7];
    const float* Wkv      = (const float*)d_in[8];
    const float* null_k   = (const float*)d_in[9];
    const float* null_v   = (const float*)d_in[10];
    const float* Wo       = (const float*)d_in[11];
    const float* bo       = (const float*)d_in[12];
    const float* Wp       = (const float*)d_in[13];
    const float* bp       = (const float*)d_in[14];
    float* out = (float*)d_out;

    const int attn_smem = 4 * 128 * KROW * 2 + (128 + 128 + 512 + 512) * (int)sizeof(float);
    cudaFuncSetAttribute(k_attn_mma, cudaFuncAttributeMaxDynamicSharedMemorySize, attn_smem);

    k_mega1<<<3457, 256>>>(emb, q_gamma, q_beta, Wo, Wp, bo, bp, Wkv, Wq);
    k_prep2<<<33, 256>>>(Wkv, null_v);
    k_ln_c<<<MPAD / 8, 256>>>(ctx, kv_gamma, kv_beta);
    k_gemm_mma<<<256 + 28, 256>>>();
    k_attn_mma<<<dim3(NC, N_SEQ / 128), 256, attn_smem>>>(null_k, cmask, out);
}

// round 9
// speedup vs baseline: 4.3284x; 1.0793x over previous
#include <cuda_runtime.h>
#include <cuda_bf16.h>
#include <math.h>

#define N_SEQ 896
#define DH    3072
#define NC    64
#define NJ    127
#define DC    1024
#define INNER 512
#define NH    8
#define HD    64
#define MPAD  8192
#define GAROW 40
#define KROW  72

// ---------------- scratch ----------------
__device__ float g_w[INNER];
__device__ float g_ep[N_SEQ];
__device__ float g_bias;
__device__ float g_wvpt[NH * DC];
__device__ float g_vpnull[NH];
__device__ float g_vpt[NC * NH * NJ];
// LN'd activations as bf16 hi/lo
__device__ __nv_bfloat16 g_a_hi[(size_t)MPAD * DC];
__device__ __nv_bfloat16 g_a_lo[(size_t)MPAD * DC];
__device__ __nv_bfloat16 g_aq_hi[(size_t)N_SEQ * DH];
__device__ __nv_bfloat16 g_aq_lo[(size_t)N_SEQ * DH];
// transposed + split weights: [n][k]
__device__ __nv_bfloat16 g_wk_hi[(size_t)INNER * DC];
__device__ __nv_bfloat16 g_wk_lo[(size_t)INNER * DC];
__device__ __nv_bfloat16 g_wq_hi[(size_t)INNER * DH];
__device__ __nv_bfloat16 g_wq_lo[(size_t)INNER * DH];
// projections as bf16 hi/lo
__device__ __nv_bfloat16 g_q_hi[(size_t)N_SEQ * INNER];
__device__ __nv_bfloat16 g_q_lo[(size_t)N_SEQ * INNER];
__device__ __nv_bfloat16 g_k_hi[(size_t)MPAD * INNER];
__device__ __nv_bfloat16 g_k_lo[(size_t)MPAD * INNER];

__device__ __forceinline__ float warpSum(float v) {
#pragma unroll
    for (int o = 16; o > 0; o >>= 1) v += __shfl_xor_sync(0xffffffffu, v, o);
    return v;
}
__device__ __forceinline__ unsigned b2u(__nv_bfloat162 h) {
    return *reinterpret_cast<unsigned*>(&h);
}
__device__ __forceinline__ unsigned smem_u32(const void* p) {
    unsigned a;
    asm("{ .reg .u64 t; cvta.to.shared.u64 t, %1; cvt.u32.u64 %0, t; }" : "=r"(a) : "l"(p));
    return a;
}
__device__ __forceinline__ void ldm_x4(unsigned* r, unsigned addr) {
    asm volatile("ldmatrix.sync.aligned.m8n8.x4.shared.b16 {%0,%1,%2,%3}, [%4];"
        : "=r"(r[0]), "=r"(r[1]), "=r"(r[2]), "=r"(r[3]) : "r"(addr));
}
__device__ __forceinline__ void ldm_x2(unsigned* r, unsigned addr) {
    asm volatile("ldmatrix.sync.aligned.m8n8.x2.shared.b16 {%0,%1}, [%2];"
        : "=r"(r[0]), "=r"(r[1]) : "r"(addr));
}
__device__ __forceinline__ void mma_bf16(float* d, const unsigned* a, const unsigned* b) {
    asm volatile("mma.sync.aligned.m16n8k16.row.col.f32.bf16.bf16.f32 "
        "{%0,%1,%2,%3}, {%4,%5,%6,%7}, {%8,%9}, {%0,%1,%2,%3};"
        : "+f"(d[0]), "+f"(d[1]), "+f"(d[2]), "+f"(d[3])
        : "r"(a[0]), "r"(a[1]), "r"(a[2]), "r"(a[3]), "r"(b[0]), "r"(b[1]));
}
__device__ __forceinline__ void cpa16(unsigned dst, const void* src) {
    asm volatile("cp.async.cg.shared.global [%0], [%1], 16;" :: "r"(dst), "l"(src));
}
#define CPA_COMMIT() asm volatile("cp.async.commit_group;" ::: "memory")
#define CPA_WAIT1()  asm volatile("cp.async.wait_group 1;" ::: "memory")
#define CPA_WAIT0()  asm volatile("cp.async.wait_group 0;" ::: "memory")

__device__ __forceinline__ void split2(float x, float y, unsigned& hi, unsigned& lo) {
    __nv_bfloat162 h = __float22bfloat162_rn(make_float2(x, y));
    __nv_bfloat162 l = __float22bfloat162_rn(make_float2(
        x - __bfloat162float(h.x), y - __bfloat162float(h.y)));
    hi = b2u(h); lo = b2u(l);
}

// ---------------- mega prologue --------------------------------------------
__global__ void k_mega1(const float* __restrict__ emb, const float* __restrict__ gamma,
                        const float* __restrict__ beta, const float* __restrict__ Wo,
                        const float* __restrict__ Wp, const float* __restrict__ bo,
                        const float* __restrict__ bp, const float* __restrict__ Wkv,
                        const float* __restrict__ Wq) {
    __shared__ float row[DH];
    __shared__ float red[26];
    int bid = blockIdx.x, t = threadIdx.x;

    if (bid < N_SEQ) {
        const float* xr = emb + (size_t)bid * DH;
        float s = 0.f, ss = 0.f, se = 0.f;
#pragma unroll
        for (int u = 0; u < 3; u++) {
            int idx = (t + u * 256) * 4;
            float4 v = *(const float4*)(xr + idx);
            float4 w = *(const float4*)(Wp + idx);
            row[idx] = v.x; row[idx+1] = v.y; row[idx+2] = v.z; row[idx+3] = v.w;
            s  += v.x + v.y + v.z + v.w;
            ss += v.x*v.x + v.y*v.y + v.z*v.z + v.w*v.w;
            se += v.x*w.x + v.y*w.y + v.z*w.z + v.w*w.w;
        }
        s = warpSum(s); ss = warpSum(ss); se = warpSum(se);
        if ((t & 31) == 0) { int w8 = t >> 5; red[w8] = s; red[8+w8] = ss; red[16+w8] = se; }
        __syncthreads();
        if (t == 0) {
            float S = 0.f, SS = 0.f, SE = 0.f;
#pragma unroll
            for (int i = 0; i < 8; i++) { S += red[i]; SS += red[8+i]; SE += red[16+i]; }
            float mu = S / DH;
            float var = SS / DH - mu * mu;
            red[24] = mu; red[25] = rsqrtf(var + 1e-5f);
            g_ep[bid] = SE;
        }
        __syncthreads();
        float mu = red[24], rstd = red[25];
#pragma unroll
        for (int u = 0; u < 3; u++) {
            int idx = (t + u * 256) * 4;
            float o0 = (row[idx]   - mu) * rstd * gamma[idx]   + beta[idx];
            float o1 = (row[idx+1] - mu) * rstd * gamma[idx+1] + beta[idx+1];
            float o2 = (row[idx+2] - mu) * rstd * gamma[idx+2] + beta[idx+2];
            float o3 = (row[idx+3] - mu) * rstd * gamma[idx+3] + beta[idx+3];
            unsigned h01, l01, h23, l23;
            split2(o0, o1, h01, l01); split2(o2, o3, h23, l23);
            size_t off = (size_t)bid * DH + idx;
            *(uint2*)(g_aq_hi + off) = make_uint2(h01, h23);
            *(uint2*)(g_aq_lo + off) = make_uint2(l01, l23);
        }
        return;
    }
    if (bid < 1409) {
        int id = bid - N_SEQ;
        const float* a = (id < 512) ? (Wo + (size_t)id * DH) : bo;
        float s = 0.f;
        for (int i = t; i < DH; i += 256) s = fmaf(a[i], Wp[i], s);
        s = warpSum(s);
        if ((t & 31) == 0) red[t >> 5] = s;
        __syncthreads();
        if (t == 0) {
            float S = 0.f;
#pragma unroll
            for (int i = 0; i < 8; i++) S += red[i];
            if (id < 512) g_w[id] = S;
            else          g_bias = S + bp[0];
        }
        return;
    }
    {
        float (*tile)[33] = (float(*)[33])row;
        const float* src; __nv_bfloat16 *dh, *dl;
        int K, ldsrc, k0, n0;
        if (bid < 1921) {
            int l = bid - 1409;
            K = DC; ldsrc = 2 * INNER; src = Wkv; dh = g_wk_hi; dl = g_wk_lo;
            k0 = (l & 31) * 32; n0 = (l >> 5) * 32;
        } else {
            int l = bid - 1921;
            K = DH; ldsrc = INNER; src = Wq; dh = g_wq_hi; dl = g_wq_lo;
            k0 = (l % 96) * 32; n0 = (l / 96) * 32;
        }
        int tx = t & 31, ty = t >> 5;
#pragma unroll
        for (int r = 0; r < 4; r++)
            tile[ty + 8 * r][tx] = src[(size_t)(k0 + ty + 8 * r) * ldsrc + n0 + tx];
        __syncthreads();
#pragma unroll
        for (int r = 0; r < 4; r++) {
            int n = n0 + ty + 8 * r;
            float v = tile[tx][ty + 8 * r];
            __nv_bfloat16 h = __float2bfloat16_rn(v);
            __nv_bfloat16 l2 = __float2bfloat16_rn(v - __bfloat162float(h));
            dh[(size_t)n * K + k0 + tx] = h;
            dl[(size_t)n * K + k0 + tx] = l2;
        }
    }
}

// ---------------- prep 2 ----------------
__global__ void k_prep2(const float* __restrict__ Wkv, const float* __restrict__ null_v) {
    int bid = blockIdx.x, t = threadIdx.x;
    if (bid < 32) {
        int gid = bid * 256 + t;
        int h = gid >> 10, i = gid & 1023;
        const float* wrow = g_w + h * HD;
        const float* src  = Wkv + (size_t)i * (2 * INNER) + INNER + h * HD;
        float s = 0.f;
#pragma unroll
        for (int d = 0; d < HD; d++) s = fmaf(src[d], wrow[d], s);
        g_wvpt[h * DC + i] = s;
    } else if (t < NH) {
        float s = 0.f;
#pragma unroll
        for (int d = 0; d < HD; d++) s = fmaf(null_v[t * HD + d], g_w[t * HD + d], s);
        g_vpnull[t] = s;
    }
}

// ---------------- LN over context rows: warp-per-row; emits bf16 hi/lo -------
__global__ __launch_bounds__(256) void k_ln_c(const float* __restrict__ x,
                                              const float* __restrict__ gamma,
                                              const float* __restrict__ beta) {
    __shared__ float wvs[NH * DC];
    int t = threadIdx.x, warp = t >> 5, lane = t & 31;
    for (int i = t; i < NH * DC; i += 256) wvs[i] = g_wvpt[i];
    __syncthreads();

    int b = blockIdx.x * 8 + warp;
    if (b >= NC * NJ) {
        if (b < MPAD) {
            uint2 z = make_uint2(0u, 0u);
#pragma unroll
            for (int c = 0; c < 8; c++) {
                size_t off = (size_t)b * DC + c * 128 + lane * 4;
                *(uint2*)(g_a_hi + off) = z;
                *(uint2*)(g_a_lo + off) = z;
            }
        }
        return;
    }
    const float* xr = x + (size_t)b * DC;
    float4 r[8];
    float s = 0.f, ss = 0.f;
#pragma unroll
    for (int c = 0; c < 8; c++) {
        r[c] = *(const float4*)(xr + c * 128 + lane * 4);
        s  += r[c].x + r[c].y + r[c].z + r[c].w;
        ss += r[c].x*r[c].x + r[c].y*r[c].y + r[c].z*r[c].z + r[c].w*r[c].w;
    }
    s = warpSum(s); ss = warpSum(ss);
    float mu = s / DC;
    float rstd = rsqrtf(ss / DC - mu * mu + 1e-5f);
#pragma unroll
    for (int c = 0; c < 8; c++) {
        int idx = c * 128 + lane * 4;
        float4 g = *(const float4*)(gamma + idx);
        float4 bb = *(const float4*)(beta + idx);
        r[c].x = (r[c].x - mu) * rstd * g.x + bb.x;
        r[c].y = (r[c].y - mu) * rstd * g.y + bb.y;
        r[c].z = (r[c].z - mu) * rstd * g.z + bb.z;
        r[c].w = (r[c].w - mu) * rstd * g.w + bb.w;
        unsigned h01, l01, h23, l23;
        split2(r[c].x, r[c].y, h01, l01); split2(r[c].z, r[c].w, h23, l23);
        size_t off = (size_t)b * DC + idx;
        *(uint2*)(g_a_hi + off) = make_uint2(h01, h23);
        *(uint2*)(g_a_lo + off) = make_uint2(l01, l23);
    }
    int cc = b / NJ, j = b % NJ;
#pragma unroll
    for (int h = 0; h < NH; h++) {
        float acc = 0.f;
#pragma unroll
        for (int c = 0; c < 8; c++) {
            int idx = h * DC + c * 128 + lane * 4;
            acc = fmaf(r[c].x, wvs[idx],   acc);
            acc = fmaf(r[c].y, wvs[idx+1], acc);
            acc = fmaf(r[c].z, wvs[idx+2], acc);
            acc = fmaf(r[c].w, wvs[idx+3], acc);
        }
        acc = warpSum(acc);
        if (lane == 0) g_vpt[((size_t)cc * NH + h) * NJ + j] = acc;
    }
}

// ---------------- HMMA GEMM v2: 128x64 tile, cp.async 2-stage pipeline --------
// smem per stage (bytes): Ah 10240 | Al 10240 | Bh 5120 | Bl 5120 = 30720; x2 stages
#define G_AL 10240
#define G_BH 20480
#define G_BL 25600
#define G_ST 30720
#define G_SMEM (2 * G_ST)

__global__ __launch_bounds__(256) void k_gemm_mma() {
    extern __shared__ char smg[];
    unsigned sbase = smem_u32(smg);
    int t = threadIdx.x, bid = blockIdx.x;

    const __nv_bfloat16 *Ahp, *Alp, *Bhp, *Blp;
    __nv_bfloat16 *Chi, *Clo;
    int Kb, m0, n0;
    if (bid < 512) {
        m0 = (bid >> 3) * 128; n0 = (bid & 7) * 64;
        Ahp = g_a_hi; Alp = g_a_lo; Kb = DC;
        Bhp = g_wk_hi; Blp = g_wk_lo; Chi = g_k_hi; Clo = g_k_lo;
    } else {
        int l = bid - 512;
        m0 = (l >> 3) * 128; n0 = (l & 7) * 64;
        Ahp = g_aq_hi; Alp = g_aq_lo; Kb = DH;
        Bhp = g_wq_hi; Blp = g_wq_lo; Chi = g_q_hi; Clo = g_q_lo;
    }
    int warp = t >> 5, lane = t & 31;
    int wm = (warp & 3) * 32, wn = (warp >> 2) * 32;

    float D[2][4][4];
#pragma unroll
    for (int i = 0; i < 2; i++)
#pragma unroll
        for (int j = 0; j < 4; j++)
#pragma unroll
            for (int k = 0; k < 4; k++) D[i][j][k] = 0.f;

    // staging indices
    int ar0 = t >> 2, ac0 = (t & 3) * 8;        // A chunk 0: rows 0..63
    int br0 = t >> 2, bc0 = (t & 3) * 8;        // B: rows 0..63
    unsigned a_off0 = (unsigned)((ar0 * GAROW + ac0) * 2);
    unsigned a_off1 = (unsigned)(((ar0 + 64) * GAROW + ac0) * 2);
    unsigned b_off  = (unsigned)((br0 * GAROW + bc0) * 2);
    const __nv_bfloat16* a0h = Ahp + (size_t)(m0 + ar0) * Kb + ac0;
    const __nv_bfloat16* a0l = Alp + (size_t)(m0 + ar0) * Kb + ac0;
    const __nv_bfloat16* a1h = Ahp + (size_t)(m0 + ar0 + 64) * Kb + ac0;
    const __nv_bfloat16* a1l = Alp + (size_t)(m0 + ar0 + 64) * Kb + ac0;
    const __nv_bfloat16* b0h = Bhp + (size_t)(n0 + br0) * Kb + bc0;
    const __nv_bfloat16* b0l = Blp + (size_t)(n0 + br0) * Kb + bc0;

    unsigned aoff = (unsigned)(((lane & 15) * GAROW + (lane >> 4) * 8) * 2);
    unsigned boff = (unsigned)(((lane & 7) * GAROW + ((lane >> 3) & 1) * 8) * 2);

    const int S = Kb / 32;
    // issue slab s into stage st
    auto issue = [&](int k0, int st) {
        unsigned base = sbase + st * G_ST;
        cpa16(base + a_off0,        a0h + k0);
        cpa16(base + a_off1,        a1h + k0);
        cpa16(base + G_AL + a_off0, a0l + k0);
        cpa16(base + G_AL + a_off1, a1l + k0);
        cpa16(base + G_BH + b_off,  b0h + k0);
        cpa16(base + G_BL + b_off,  b0l + k0);
        CPA_COMMIT();
    };

    issue(0, 0);
    for (int s = 0; s < S; s++) {
        if (s + 1 < S) { issue((s + 1) * 32, (s + 1) & 1); CPA_WAIT1(); }
        else           { CPA_WAIT0(); }
        __syncthreads();
        unsigned ab = sbase + (s & 1) * G_ST;
#pragma unroll
        for (int ks = 0; ks < 32; ks += 16) {
            unsigned ah[2][4], al[2][4], bh2[4][2], bl2[4][2];
#pragma unroll
            for (int mt = 0; mt < 2; mt++) {
                unsigned rowb = (unsigned)(((wm + mt * 16) * GAROW + ks) * 2);
                ldm_x4(ah[mt], ab + rowb + aoff);
                ldm_x4(al[mt], ab + G_AL + rowb + aoff);
            }
#pragma unroll
            for (int nt = 0; nt < 4; nt++) {
                unsigned rowb = (unsigned)(((wn + nt * 8) * GAROW + ks) * 2);
                ldm_x2(bh2[nt], ab + G_BH + rowb + boff);
                ldm_x2(bl2[nt], ab + G_BL + rowb + boff);
            }
#pragma unroll
            for (int mt = 0; mt < 2; mt++)
#pragma unroll
                for (int nt = 0; nt < 4; nt++) {
                    mma_bf16(D[mt][nt], ah[mt], bh2[nt]);
                    mma_bf16(D[mt][nt], al[mt], bh2[nt]);
                    mma_bf16(D[mt][nt], ah[mt], bl2[nt]);
                }
        }
        __syncthreads();
    }
    // ---- epilogue: fp32 -> bf16 hi/lo ----
#pragma unroll
    for (int mt = 0; mt < 2; mt++) {
        int r0 = m0 + wm + mt * 16 + (lane >> 2);
#pragma unroll
        for (int nt = 0; nt < 4; nt++) {
            int col = n0 + wn + nt * 8 + 2 * (lane & 3);
#pragma unroll
            for (int half = 0; half < 2; half++) {
                unsigned hh, ll;
                split2(D[mt][nt][half * 2], D[mt][nt][half * 2 + 1], hh, ll);
                size_t off = (size_t)(r0 + half * 8) * INNER + col;
                *(unsigned*)(Chi + off) = hh;
                *(unsigned*)(Clo + off) = ll;
            }
        }
    }
}

// ---------------- attention via HMMA ----------------
__global__ __launch_bounds__(256) void k_attn_mma(const float* __restrict__ null_k,
                                                  const int* __restrict__ mask,
                                                  float* __restrict__ out) {
    extern __shared__ char smc[];
    __nv_bfloat16* Qh_s = (__nv_bfloat16*)smc;
    __nv_bfloat16* Ql_s = Qh_s + 128 * KROW;
    __nv_bfloat16* Kh_s = Ql_s + 128 * KROW;
    __nv_bfloat16* Kl_s = Kh_s + 128 * KROW;
    float* validS = (float*)(Kl_s + 128 * KROW);
    float* vps    = validS + 128;
    float* RedS   = vps + 128;
    float* RedT   = RedS + 512;

    int c = blockIdx.x, n0 = blockIdx.y * 128;
    int t = threadIdx.x;
    int warp = t >> 5, lane = t & 31;
    int wm = (warp & 1) * 64, wn = (warp >> 1) * 32;
    int wg = warp >> 1;

    if (t < 128) validS[t] = (t == 0 || mask[t - 1] != 0) ? 1.f : 0.f;
    float racc = 0.f;

    int srow = t >> 1, skc = (t & 1) * 32;
    const __nv_bfloat16* qh = g_q_hi + (size_t)(n0 + srow) * INNER + skc;
    const __nv_bfloat16* ql = g_q_lo + (size_t)(n0 + srow) * INNER + skc;
    const __nv_bfloat16* kh = g_k_hi + (size_t)(c * NJ + srow - 1) * INNER + skc;
    const __nv_bfloat16* kl = g_k_lo + (size_t)(c * NJ + srow - 1) * INNER + skc;

    unsigned qh_b = smem_u32(Qh_s), ql_b = smem_u32(Ql_s);
    unsigned kh_b = smem_u32(Kh_s), kl_b = smem_u32(Kl_s);
    unsigned aoff = (unsigned)(((lane & 15) * KROW + (lane >> 4) * 8) * 2);
    unsigned boff = (unsigned)(((lane & 7) * KROW + ((lane >> 3) & 1) * 8) * 2);

    for (int h = 0; h < NH; h++) {
        {
            int e = srow * KROW + skc;
            const uint4* s0 = (const uint4*)(qh + h * HD);
            const uint4* s1 = (const uint4*)(ql + h * HD);
            uint4* d0 = (uint4*)(Qh_s + e);
            uint4* d1 = (uint4*)(Ql_s + e);
#pragma unroll
            for (int u = 0; u < 4; u++) { d0[u] = s0[u]; d1[u] = s1[u]; }
        }
        if (srow == 0) {
#pragma unroll
            for (int u = 0; u < 32; u++) {
                float v = null_k[h * HD + skc + u];
                __nv_bfloat16 hb = __float2bfloat16_rn(v);
                Kh_s[skc + u] = hb;
                Kl_s[skc + u] = __float2bfloat16_rn(v - __bfloat162float(hb));
            }
        } else {
            int e = srow * KROW + skc;
            const uint4* s0 = (const uint4*)(kh + h * HD);
            const uint4* s1 = (const uint4*)(kl + h * HD);
            uint4* d0 = (uint4*)(Kh_s + e);
            uint4* d1 = (uint4*)(Kl_s + e);
#pragma unroll
            for (int u = 0; u < 4; u++) { d0[u] = s0[u]; d1[u] = s1[u]; }
        }
        if (t < 128)
            vps[t] = (t == 0) ? g_vpnull[h] : g_vpt[((size_t)c * NH + h) * NJ + t - 1];
        __syncthreads();

        float D[4][4][4];
#pragma unroll
        for (int i = 0; i < 4; i++)
#pragma unroll
            for (int j = 0; j < 4; j++)
#pragma unroll
                for (int k = 0; k < 4; k++) D[i][j][k] = 0.f;
#pragma unroll
        for (int ks = 0; ks < 64; ks += 16) {
            unsigned ah[4][4], al[4][4], bh2[4][2], bl2[4][2];
#pragma unroll
            for (int mt = 0; mt < 4; mt++) {
                unsigned rowb = (unsigned)(((wm + mt * 16) * KROW + ks) * 2);
                ldm_x4(ah[mt], qh_b + rowb + aoff);
                ldm_x4(al[mt], ql_b + rowb + aoff);
            }
#pragma unroll
            for (int nt = 0; nt < 4; nt++) {
                unsigned rowb = (unsigned)(((wn + nt * 8) * KROW + ks) * 2);
                ldm_x2(bh2[nt], kh_b + rowb + boff);
                ldm_x2(bl2[nt], kl_b + rowb + boff);
            }
#pragma unroll
            for (int mt = 0; mt < 4; mt++)
#pragma unroll
                for (int nt = 0; nt < 4; nt++) {
                    mma_bf16(D[mt][nt], ah[mt], bh2[nt]);
                    mma_bf16(D[mt][nt], al[mt], bh2[nt]);
                    mma_bf16(D[mt][nt], ah[mt], bl2[nt]);
                }
        }

        float rS[4][2], rT[4][2];
#pragma unroll
        for (int mt = 0; mt < 4; mt++) { rS[mt][0] = rS[mt][1] = rT[mt][0] = rT[mt][1] = 0.f; }
#pragma unroll
        for (int nt = 0; nt < 4; nt++) {
            int c0 = wn + nt * 8 + 2 * (lane & 3);
            float vl0 = validS[c0], vl1 = validS[c0 + 1];
            float vp0 = vps[c0],    vp1 = vps[c0 + 1];
#pragma unroll
            for (int mt = 0; mt < 4; mt++) {
                float e00 = vl0 * __expf(D[mt][nt][0] * 0.125f);
                float e01 = vl1 * __expf(D[mt][nt][1] * 0.125f);
                float e10 = vl0 * __expf(D[mt][nt][2] * 0.125f);
                float e11 = vl1 * __expf(D[mt][nt][3] * 0.125f);
                rS[mt][0] += e00 + e01;
                rT[mt][0] += e00 * vp0 + e01 * vp1;
                rS[mt][1] += e10 + e11;
                rT[mt][1] += e10 * vp0 + e11 * vp1;
            }
        }
#pragma unroll
        for (int mt = 0; mt < 4; mt++)
#pragma unroll
            for (int half = 0; half < 2; half++) {
                float s = rS[mt][half], tt = rT[mt][half];
                s  += __shfl_xor_sync(0xffffffffu, s, 1);
                s  += __shfl_xor_sync(0xffffffffu, s, 2);
                tt += __shfl_xor_sync(0xffffffffu, tt, 1);
                tt += __shfl_xor_sync(0xffffffffu, tt, 2);
                if ((lane & 3) == 0) {
                    int row = wm + mt * 16 + (lane >> 2) + half * 8;
                    RedS[row * 4 + wg] = s;
                    RedT[row * 4 + wg] = tt;
                }
            }
        __syncthreads();
        if (t < 128) {
            float S = RedS[t*4] + RedS[t*4+1] + RedS[t*4+2] + RedS[t*4+3];
            float T = RedT[t*4] + RedT[t*4+1] + RedT[t*4+2] + RedT[t*4+3];
            racc += T / S;
        }
        __syncthreads();
    }
    if (t < 128) {
        int n = n0 + t;
        float x = g_ep[n] + g_bias + racc;
        out[(size_t)n * NC + c] = fmaxf(x, 0.f) + log1pf(__expf(-fabsf(x)));
    }
}

// ---------------- launch ----------------
extern "C" void kernel_launch(void* const* d_in, const int* in_sizes, int n_in,
                              void* d_out, int out_size) {
    const float* emb      = (const float*)d_in[0];
    const float* ctx      = (const float*)d_in[1];
    const int*   cmask    = (const int*)d_in[2];
    const float* q_gamma  = (const float*)d_in[3];
    const float* q_beta   = (const float*)d_in[4];
    const float* kv_gamma = (const float*)d_in[5];
    const float* kv_beta  = (const float*)d_in[6];
    const float* Wq       = (const float*)d_in[7];
    const float* Wkv      = (const float*)d_in[8];
    const float* null_k   = (const float*)d_in[9];
    const float* null_v   = (const float*)d_in[10];
    const float* Wo       = (const float*)d_in[11];
    const float* bo       = (const float*)d_in[12];
    const float* Wp       = (const float*)d_in[13];
    const float* bp       = (const float*)d_in[14];
    float* out = (float*)d_out;

    const int attn_smem = 4 * 128 * KROW * 2 + (128 + 128 + 512 + 512) * (int)sizeof(float);
    cudaFuncSetAttribute(k_attn_mma, cudaFuncAttributeMaxDynamicSharedMemorySize, attn_smem);
    cudaFuncSetAttribute(k_gemm_mma, cudaFuncAttributeMaxDynamicSharedMemorySize, G_SMEM);

    k_mega1<<<3457, 256>>>(emb, q_gamma, q_beta, Wo, Wp, bo, bp, Wkv, Wq);
    k_prep2<<<33, 256>>>(Wkv, null_v);
    k_ln_c<<<MPAD / 8, 256>>>(ctx, kv_gamma, kv_beta);
    k_gemm_mma<<<512 + 56, 256, G_SMEM>>>();
    k_attn_mma<<<dim3(NC, N_SEQ / 128), 256, attn_smem>>>(null_k, cmask, out);
}